// round 5
// baseline (speedup 1.0000x reference)
#include <cuda_runtime.h>
#include <cuda_bf16.h>
#include <cstdint>
#include <cstddef>

// Problem constants
#define BATCH 32
#define NT    256
#define NS    4096
#define CDIM  256
#define TOPKN 32
#define NWIN  64      // 8x8 windows
#define WTOK  64      // tokens per window (8x8)

// ---------------- device scratch (no allocations allowed) ----------------
__device__ float g_WdT[CDIM * CDIM];   // WdT[k*256 + o] = Wd[o*256 + k]
__device__ float g_WuT[CDIM * CDIM];   // WuT[c*256 + o] = Wu[o*256 + c]
__device__ float g_zmax[BATCH * CDIM];
__device__ float g_simw[BATCH * NWIN];
__device__ int   g_idx[BATCH * TOPKN];

// ---------------- K0: transpose both weight matrices ----------------
__global__ void k_transpose(const float* __restrict__ Wd,
                            const float* __restrict__ Wu) {
    const int i = blockIdx.x * 256 + threadIdx.x;  // i = k*256 + o
    const int k = i >> 8;
    const int o = i & 255;
    g_WdT[i] = Wd[o * 256 + k];
    g_WuT[i] = Wu[o * 256 + k];
}

// ---------------- K1: z_max over Nt ----------------
__global__ void k_zmax(const float* __restrict__ z) {
    const int b = blockIdx.x;
    const int c = threadIdx.x;
    const float* zb = z + (size_t)b * NT * CDIM + c;
    float m = zb[0];
    #pragma unroll 8
    for (int n = 1; n < NT; ++n) m = fmaxf(m, zb[(size_t)n * CDIM]);
    g_zmax[b * CDIM + c] = m;
}

// ---------------- K2: per-window mean similarity ----------------
// grid: B*64 blocks, 256 threads (8 warps, each warp does 8 tokens)
__global__ void k_sim(const float* __restrict__ x) {
    const int bw = blockIdx.x;
    const int b = bw >> 6;
    const int win = bw & 63;
    const int wh = win >> 3, ww = win & 7;

    __shared__ float zm[CDIM];
    __shared__ float tok[WTOK];

    const int tid = threadIdx.x;
    zm[tid] = g_zmax[b * CDIM + tid];
    __syncthreads();

    const int w = tid >> 5, l = tid & 31;
    const float* xb = x + ((size_t)b * NS + (size_t)wh * 512 + (size_t)ww * 8) * CDIM;
    const float4* zm4 = (const float4*)zm;
    const float4 z0 = zm4[2 * l];
    const float4 z1 = zm4[2 * l + 1];

    #pragma unroll
    for (int m = 0; m < 8; ++m) {
        // token (i=w, j=m) inside the window
        const float4* row = (const float4*)(xb + (size_t)(w * 64 + m) * CDIM);
        const float4 v0 = row[2 * l];
        const float4 v1 = row[2 * l + 1];
        float a = v0.x * z0.x + v0.y * z0.y + v0.z * z0.z + v0.w * z0.w
                + v1.x * z1.x + v1.y * z1.y + v1.z * z1.z + v1.w * z1.w;
        #pragma unroll
        for (int off = 16; off; off >>= 1) a += __shfl_xor_sync(0xffffffffu, a, off);
        if (l == 0) tok[w * 8 + m] = a;
    }
    __syncthreads();
    if (tid < 32) {
        float v = tok[tid] + tok[tid + 32];
        #pragma unroll
        for (int off = 16; off; off >>= 1) v += __shfl_xor_sync(0xffffffffu, v, off);
        if (tid == 0) g_simw[b * NWIN + win] = v * (1.0f / (256.0f * 64.0f));
    }
}

// ---------------- K3: top-k (descending value, tie -> lower index) ----------------
__global__ void k_topk() {
    const int b = blockIdx.x;
    const int t = threadIdx.x;            // 64 threads
    __shared__ float v[NWIN];
    v[t] = g_simw[b * NWIN + t];
    __syncthreads();
    if (t < 32) {
        for (int k = 0; k < TOPKN; ++k) {
            float a = v[t], c = v[t + 32];
            float bestv; int besti;
            if (a >= c) { bestv = a; besti = t; } else { bestv = c; besti = t + 32; }
            #pragma unroll
            for (int off = 16; off; off >>= 1) {
                float ov = __shfl_xor_sync(0xffffffffu, bestv, off);
                int   oi = __shfl_xor_sync(0xffffffffu, besti, off);
                if (ov > bestv || (ov == bestv && oi < besti)) { bestv = ov; besti = oi; }
            }
            besti = __shfl_sync(0xffffffffu, besti, 0);
            if (t == 0) {
                g_idx[b * TOPKN + k] = besti;
                v[besti] = -__int_as_float(0x7f800000);  // -inf
            }
            __syncwarp();
        }
    }
}

// ---------------- fused per-window GEMM helper ----------------
// Thread `o` computes output column o over 64 rows, reduction over 256 channels.
// A in smem is column(k)-major with XOR-swizzled float4 groups:
//   element (k, r) at word  k*64 + (((r>>2) ^ (k&15)) << 2) + (r&3)
// acc[m] packs rows (2m, 2m+1) as f32x2 in a 64-bit register.
__device__ __forceinline__ void gemm_col(const float* sm,
                                         const float* __restrict__ Wt,
                                         int o,
                                         unsigned long long acc[32]) {
    #pragma unroll
    for (int m = 0; m < 32; ++m) acc[m] = 0ULL;
    const float* wcol = Wt + o;
    #pragma unroll 1
    for (int kb = 0; kb < 16; ++kb) {
        const float* smb = sm + (kb << 10);            // 16 columns * 64 floats
        const float* wb  = wcol + (kb << 12);          // 16 rows * 256
        #pragma unroll
        for (int kq = 0; kq < 16; ++kq) {
            const float wv = __ldg(wb + (kq << 8));
            unsigned long long w2;
            asm("mov.b64 %0, {%1,%1};" : "=l"(w2) : "f"(wv));
            const float* colp = smb + (kq << 6);
            #pragma unroll
            for (int f = 0; f < 16; ++f) {
                const ulonglong2 a =
                    *reinterpret_cast<const ulonglong2*>(colp + ((f ^ kq) << 2));
                asm("fma.rn.f32x2 %0, %1, %2, %0;" : "+l"(acc[2 * f])     : "l"(a.x), "l"(w2));
                asm("fma.rn.f32x2 %0, %1, %2, %0;" : "+l"(acc[2 * f + 1]) : "l"(a.y), "l"(w2));
            }
        }
    }
}

__device__ __forceinline__ int swz(int r, int sw) {
    return ((((r >> 2) ^ sw) << 2) | (r & 3));
}

// ---------------- K4: gather + GEMM1 + shift + GEMM2 + residual ----------------
__global__ void __launch_bounds__(256, 2) k_main(const float* __restrict__ x,
                                                 const float* __restrict__ bd,
                                                 const float* __restrict__ bu,
                                                 float* __restrict__ out) {
    extern __shared__ float sm[];   // 64 cols-of-k? no: 256 columns(k) x 64 rows = 16384 floats
    const int g = blockIdx.x;
    const int b = g >> 5;
    const int kk = g & 31;
    const int win = g_idx[b * TOPKN + kk];
    const int wh = win >> 3, ww = win & 7;
    const int o = threadIdx.x;          // output channel / smem column owner
    const int sw = o & 15;

    const float* xb = x + ((size_t)b * NS + (size_t)wh * 512 + (size_t)ww * 8) * CDIM;

    // ---- gather xe window (64 x 256) into swizzled k-major smem ----
    #pragma unroll
    for (int r = 0; r < 64; ++r) {
        const int goff = ((r >> 3) * 64 + (r & 7)) * CDIM;  // compile-time per r
        const float v = __ldg(xb + goff + o);
        sm[(o << 6) + swz(r, sw)] = v;
    }
    __syncthreads();

    unsigned long long acc[32];

    // ---- GEMM1: t[:, o] = xe @ Wd^T ----
    gemm_col(sm, g_WdT, o, acc);

    // ---- t = acc + bd; spatial shift by channel group; write back to sm ----
    const float bdv = __ldg(bd + o);
    float t[64];
    #pragma unroll
    for (int m = 0; m < 32; ++m) {
        float lo, hi;
        asm("mov.b64 {%0,%1}, %2;" : "=f"(lo), "=f"(hi) : "l"(acc[m]));
        t[2 * m]     = lo + bdv;
        t[2 * m + 1] = hi + bdv;
    }
    __syncthreads();   // all GEMM1 reads of sm finished before overwrite

    const int grp = o >> 6;   // uniform within a warp (no divergence)
    if (grp == 0) {
        // s0[i,j] = t[i, j+1] (j<7 else 0)
        #pragma unroll
        for (int r = 0; r < 64; ++r) {
            float v = 0.0f;
            if ((r & 7) != 7) v = t[((r & 7) != 7) ? (r + 1) : 0];
            sm[(o << 6) + swz(r, sw)] = v;
        }
    } else if (grp == 1) {
        // s1[i,j] = t[i, j-1] (j>0 else 0)
        #pragma unroll
        for (int r = 0; r < 64; ++r) {
            float v = 0.0f;
            if ((r & 7) != 0) v = t[((r & 7) != 0) ? (r - 1) : 0];
            sm[(o << 6) + swz(r, sw)] = v;
        }
    } else if (grp == 2) {
        // s2[i,j] = t[i+1, j] (i<7 else 0)
        #pragma unroll
        for (int r = 0; r < 64; ++r) {
            float v = 0.0f;
            if (r < 56) v = t[(r < 56) ? (r + 8) : 0];
            sm[(o << 6) + swz(r, sw)] = v;
        }
    } else {
        // s3[i,j] = t[i-1, j] (i>0 else 0)
        #pragma unroll
        for (int r = 0; r < 64; ++r) {
            float v = 0.0f;
            if (r >= 8) v = t[(r >= 8) ? (r - 8) : 0];
            sm[(o << 6) + swz(r, sw)] = v;
        }
    }
    __syncthreads();

    // ---- GEMM2: up[:, o] = sh @ Wu^T ----
    gemm_col(sm, g_WuT, o, acc);

    // ---- epilogue: out = xe + up + bu ----
    const float buv = __ldg(bu + o);
    float* ob = out + ((size_t)b * (TOPKN * WTOK) + (size_t)kk * WTOK) * CDIM + o;
    #pragma unroll
    for (int m = 0; m < 32; ++m) {
        float lo, hi;
        asm("mov.b64 {%0,%1}, %2;" : "=f"(lo), "=f"(hi) : "l"(acc[m]));
        const int r0 = 2 * m, r1 = 2 * m + 1;
        const int g0off = ((r0 >> 3) * 64 + (r0 & 7)) * CDIM;
        const int g1off = ((r1 >> 3) * 64 + (r1 & 7)) * CDIM;
        ob[(size_t)r0 * CDIM] = __ldg(xb + g0off + o) + lo + buv;
        ob[(size_t)r1 * CDIM] = __ldg(xb + g1off + o) + hi + buv;
    }
}

// ---------------- launcher ----------------
extern "C" void kernel_launch(void* const* d_in, const int* in_sizes, int n_in,
                              void* d_out, int out_size) {
    const float* z  = (const float*)d_in[0];
    const float* x  = (const float*)d_in[1];
    const float* Wd = (const float*)d_in[2];
    const float* bd = (const float*)d_in[3];
    const float* Wu = (const float*)d_in[4];
    const float* bu = (const float*)d_in[5];
    float* out = (float*)d_out;

    k_transpose<<<256, 256>>>(Wd, Wu);
    k_zmax<<<BATCH, 256>>>(z);
    k_sim<<<BATCH * NWIN, 256>>>(x);
    k_topk<<<BATCH, 64>>>();

    static int smem_set = 0;
    // cudaFuncSetAttribute is idempotent and capture-safe (not a stream op);
    // call unconditionally to stay deterministic.
    (void)smem_set;
    cudaFuncSetAttribute(k_main, cudaFuncAttributeMaxDynamicSharedMemorySize, 65536);
    k_main<<<BATCH * TOPKN, 256, 65536>>>(x, bd, bu, out);
}

// round 8
// speedup vs baseline: 2.0950x; 2.0950x over previous
#include <cuda_runtime.h>
#include <cuda_bf16.h>
#include <cstdint>
#include <cstddef>

// Problem constants
#define BATCH 32
#define NT    256
#define NS    4096
#define CDIM  256
#define TOPKN 32
#define NWIN  64      // 8x8 windows of 8x8 tokens

// ---------------- device scratch ----------------
__device__ float g_zmax[BATCH * CDIM];
__device__ float g_simw[BATCH * NWIN];
__device__ int   g_idx[BATCH * TOPKN];
// bf16 hi/lo chunk images of Wd (cc 0..7) and Wu (cc 8..15):
// per cc: [hi 256x40][lo 256x40] bf16, rows padded 32->40 elements.
__device__ __align__(16) uint8_t g_B[16 * 2 * 20480];

// ---------------- asm helpers ----------------
__device__ __forceinline__ uint32_t s2u(const void* p) {
    uint32_t a;
    asm("{ .reg .u64 t; cvta.to.shared.u64 t, %1; cvt.u32.u64 %0, t; }"
        : "=r"(a) : "l"(p));
    return a;
}

__device__ __forceinline__ void ldsm_x4(uint32_t* r, uint32_t addr) {
    asm volatile("ldmatrix.sync.aligned.m8n8.x4.shared.b16 {%0,%1,%2,%3}, [%4];"
        : "=r"(r[0]), "=r"(r[1]), "=r"(r[2]), "=r"(r[3]) : "r"(addr));
}

// NON-trans x2: B stored [n][k] row-major IS the .col operand layout;
// r0 <- tile addressed by lanes 0-7 (k0-7), r1 <- lanes 8-15 (k8-15).
__device__ __forceinline__ void ldsm_x2(uint32_t* r, uint32_t addr) {
    asm volatile("ldmatrix.sync.aligned.m8n8.x2.shared.b16 {%0,%1}, [%2];"
        : "=r"(r[0]), "=r"(r[1]) : "r"(addr));
}

__device__ __forceinline__ void mma_bf16(float* c, const uint32_t* a, const uint32_t* b) {
    asm volatile(
        "mma.sync.aligned.m16n8k16.row.col.f32.bf16.bf16.f32 "
        "{%0,%1,%2,%3}, {%4,%5,%6,%7}, {%8,%9}, {%0,%1,%2,%3};"
        : "+f"(c[0]), "+f"(c[1]), "+f"(c[2]), "+f"(c[3])
        : "r"(a[0]), "r"(a[1]), "r"(a[2]), "r"(a[3]), "r"(b[0]), "r"(b[1]));
}

__device__ __forceinline__ void cp16(uint32_t dst, const void* src) {
    asm volatile("cp.async.cg.shared.global [%0], [%1], 16;"
                 :: "r"(dst), "l"(src) : "memory");
}
#define CP_COMMIT() asm volatile("cp.async.commit_group;" ::: "memory")
#define CP_WAIT(n)  asm volatile("cp.async.wait_group %0;" :: "n"(n) : "memory")

// ---------------- K0: bf16 hi/lo split + pad the weights ----------------
// grid 16 (= mat*8 + chunk), block 256: thread = output row n
__global__ void k_prepw(const float* __restrict__ Wd, const float* __restrict__ Wu) {
    const int cc  = blockIdx.x;
    const int mat = cc >> 3;
    const int c   = cc & 7;
    const float* W = mat ? Wu : Wd;
    const int n = threadIdx.x;
    const float* src = W + n * 256 + c * 32;
    uint32_t* hi = (uint32_t*)(g_B + (size_t)cc * 40960 + n * 80);
    uint32_t* lo = (uint32_t*)((uint8_t*)hi + 20480);
    #pragma unroll
    for (int kk = 0; kk < 16; ++kk) {
        const float2 w2 = *(const float2*)(src + 2 * kk);
        __nv_bfloat162 h2 = __float22bfloat162_rn(w2);
        float2 r2;
        r2.x = w2.x - __bfloat162float(h2.x);
        r2.y = w2.y - __bfloat162float(h2.y);
        __nv_bfloat162 l2 = __float22bfloat162_rn(r2);
        hi[kk] = *(uint32_t*)&h2;
        lo[kk] = *(uint32_t*)&l2;
    }
}

// ---------------- K1: z_max over Nt ----------------
__global__ void k_zmax(const float* __restrict__ z) {
    const int b = blockIdx.x;
    const int c = threadIdx.x;
    const float* zb = z + (size_t)b * NT * CDIM + c;
    float m = zb[0];
    #pragma unroll 8
    for (int n = 1; n < NT; ++n) m = fmaxf(m, zb[(size_t)n * CDIM]);
    g_zmax[b * CDIM + c] = m;
}

// ---------------- K2: per-window mean similarity ----------------
__global__ void k_sim(const float* __restrict__ x) {
    const int bw = blockIdx.x;
    const int b = bw >> 6;
    const int win = bw & 63;
    const int wh = win >> 3, ww = win & 7;

    __shared__ float zm[CDIM];
    __shared__ float tok[64];

    const int tid = threadIdx.x;
    zm[tid] = g_zmax[b * CDIM + tid];
    __syncthreads();

    const int w = tid >> 5, l = tid & 31;
    const float* xb = x + ((size_t)b * NS + (size_t)wh * 512 + (size_t)ww * 8) * CDIM;
    const float4* zm4 = (const float4*)zm;
    const float4 z0 = zm4[2 * l];
    const float4 z1 = zm4[2 * l + 1];

    #pragma unroll
    for (int m = 0; m < 8; ++m) {
        const float4* row = (const float4*)(xb + (size_t)(w * 64 + m) * CDIM);
        const float4 v0 = row[2 * l];
        const float4 v1 = row[2 * l + 1];
        float a = v0.x * z0.x + v0.y * z0.y + v0.z * z0.z + v0.w * z0.w
                + v1.x * z1.x + v1.y * z1.y + v1.z * z1.z + v1.w * z1.w;
        #pragma unroll
        for (int off = 16; off; off >>= 1) a += __shfl_xor_sync(0xffffffffu, a, off);
        if (l == 0) tok[w * 8 + m] = a;
    }
    __syncthreads();
    if (tid < 32) {
        float v = tok[tid] + tok[tid + 32];
        #pragma unroll
        for (int off = 16; off; off >>= 1) v += __shfl_xor_sync(0xffffffffu, v, off);
        if (tid == 0) g_simw[b * NWIN + win] = v * (1.0f / (256.0f * 64.0f));
    }
}

// ---------------- K3: top-k (descending, tie -> lower index) ----------------
__global__ void k_topk() {
    const int b = blockIdx.x;
    const int t = threadIdx.x;            // 64 threads
    __shared__ float v[NWIN];
    v[t] = g_simw[b * NWIN + t];
    __syncthreads();
    if (t < 32) {
        for (int k = 0; k < TOPKN; ++k) {
            float a = v[t], c = v[t + 32];
            float bestv; int besti;
            if (a >= c) { bestv = a; besti = t; } else { bestv = c; besti = t + 32; }
            #pragma unroll
            for (int off = 16; off; off >>= 1) {
                float ov = __shfl_xor_sync(0xffffffffu, bestv, off);
                int   oi = __shfl_xor_sync(0xffffffffu, besti, off);
                if (ov > bestv || (ov == bestv && oi < besti)) { bestv = ov; besti = oi; }
            }
            besti = __shfl_sync(0xffffffffu, besti, 0);
            if (t == 0) {
                g_idx[b * TOPKN + k] = besti;
                v[besti] = -__int_as_float(0x7f800000);
            }
            __syncwarp();
        }
    }
}

// ---------------- K4: fused mma.sync main ----------------
// SMEM (dynamic, bytes):
//   A_hi: [128 rows][264 elem bf16] = 67584   @ 0
//   A_lo: same                                @ 67584
//   B buffers: 2 x ([hi 256x40][lo 256x40])   @ 135168  (40960 each)
#define SM_AH  0
#define SM_AL  67584
#define SM_B   135168
#define SM_TOT 217088
#define ASTRIDE 528   // bytes per A row (264 bf16)
#define BSTRIDE 80    // bytes per B row (40 bf16)

__global__ void __launch_bounds__(512, 1) k_main(const float* __restrict__ x,
                                                 const float* __restrict__ bd,
                                                 const float* __restrict__ bu,
                                                 float* __restrict__ out) {
    extern __shared__ uint8_t smem[];
    const uint32_t sb = s2u(smem);
    const int tid  = threadIdx.x;
    const int lane = tid & 31;
    const int w    = tid >> 5;            // warp 0..15
    const int m0   = (w >> 3) * 64;       // warp M base (0 or 64)
    const int n0   = (w & 7) * 32;        // warp N base

    // kick off B chunk 0 prefetch immediately
    {
        const uint8_t* src = g_B;
        const uint32_t dst = sb + SM_B;
        #pragma unroll
        for (int i = 0; i < 5; ++i) cp16(dst + (tid + 512 * i) * 16, src + (tid + 512 * i) * 16);
        CP_COMMIT();
    }

    // window bases
    const int w0g = 2 * blockIdx.x, w1g = w0g + 1;
    const int winA = g_idx[(w0g >> 5) * TOPKN + (w0g & 31)];
    const int winB = g_idx[(w1g >> 5) * TOPKN + (w1g & 31)];
    const float* xbA = x + ((size_t)(w0g >> 5) * NS + (size_t)(winA >> 3) * 512 + (size_t)(winA & 7) * 8) * CDIM;
    const float* xbB = x + ((size_t)(w1g >> 5) * NS + (size_t)(winB >> 3) * 512 + (size_t)(winB & 7) * 8) * CDIM;

    // ---- gather xe (128 rows x 256 ch) into bf16 hi/lo smem ----
    {
        const int c2 = (tid & 127) * 2;          // channel pair
        const int rg = tid >> 7;                 // row group 0..3
        #pragma unroll 4
        for (int r0 = 0; r0 < 32; ++r0) {
            const int row = rg * 32 + r0;
            const int r = row & 63;
            const float* xb = (row < 64) ? xbA : xbB;
            const float2 v = *(const float2*)(xb + (size_t)((r >> 3) * 64 + (r & 7)) * CDIM + c2);
            __nv_bfloat162 h2 = __float22bfloat162_rn(v);
            float2 rr;
            rr.x = v.x - __bfloat162float(h2.x);
            rr.y = v.y - __bfloat162float(h2.y);
            __nv_bfloat162 l2 = __float22bfloat162_rn(rr);
            *(uint32_t*)(smem + SM_AH + row * ASTRIDE + c2 * 2) = *(uint32_t*)&h2;
            *(uint32_t*)(smem + SM_AL + row * ASTRIDE + c2 * 2) = *(uint32_t*)&l2;
        }
    }
    __syncthreads();

    // ldmatrix lane addresses
    const uint32_t aRow = (uint32_t)(m0 + (lane & 7) + ((lane >> 3) & 1) * 8);
    const uint32_t aKb  = (uint32_t)(((lane >> 4) & 1) * 16);
    const uint32_t aAddrH = sb + SM_AH + aRow * ASTRIDE + aKb;
    const uint32_t aAddrL = aAddrH + (SM_AL - SM_AH);
    const uint32_t bAddr  = sb + SM_B + (uint32_t)(n0 + (lane & 7)) * BSTRIDE
                          + (uint32_t)(((lane >> 3) & 1) * 16);

    float acc[4][4][4];
    #pragma unroll
    for (int mi = 0; mi < 4; ++mi)
        #pragma unroll
        for (int nj = 0; nj < 4; ++nj)
            #pragma unroll
            for (int q = 0; q < 4; ++q) acc[mi][nj][q] = 0.0f;

    // ---- 16 k32-chunk stream: cc 0..7 = GEMM1 (Wd), 8..15 = GEMM2 (Wu) ----
    #pragma unroll 1
    for (int cc = 0; cc < 16; ++cc) {
        if (cc < 15) {
            const uint8_t* src = g_B + (size_t)(cc + 1) * 40960;
            const uint32_t dst = sb + SM_B + (uint32_t)((cc + 1) & 1) * 40960;
            #pragma unroll
            for (int i = 0; i < 5; ++i) cp16(dst + (tid + 512 * i) * 16, src + (tid + 512 * i) * 16);
            CP_COMMIT();
            CP_WAIT(1);
        } else {
            CP_WAIT(0);
        }
        __syncthreads();

        const uint32_t bufb = bAddr + (uint32_t)(cc & 1) * 40960;
        const uint32_t kChunkA = (uint32_t)((cc & 7) * 64);   // A byte offset of chunk

        #pragma unroll
        for (int ks = 0; ks < 2; ++ks) {
            const uint32_t ka = kChunkA + (uint32_t)ks * 32;
            uint32_t ah[4][4], al[4][4];
            #pragma unroll
            for (int mi = 0; mi < 4; ++mi) {
                ldsm_x4(ah[mi], aAddrH + (uint32_t)mi * (16 * ASTRIDE) + ka);
                ldsm_x4(al[mi], aAddrL + (uint32_t)mi * (16 * ASTRIDE) + ka);
            }
            uint32_t bh[4][2];
            #pragma unroll
            for (int nj = 0; nj < 4; ++nj)
                ldsm_x2(bh[nj], bufb + (uint32_t)nj * (8 * BSTRIDE) + (uint32_t)ks * 32);
            #pragma unroll
            for (int mi = 0; mi < 4; ++mi)
                #pragma unroll
                for (int nj = 0; nj < 4; ++nj) mma_bf16(acc[mi][nj], ah[mi], bh[nj]);
            #pragma unroll
            for (int mi = 0; mi < 4; ++mi)
                #pragma unroll
                for (int nj = 0; nj < 4; ++nj) mma_bf16(acc[mi][nj], al[mi], bh[nj]);
            uint32_t bl[4][2];
            #pragma unroll
            for (int nj = 0; nj < 4; ++nj)
                ldsm_x2(bl[nj], bufb + 20480 + (uint32_t)nj * (8 * BSTRIDE) + (uint32_t)ks * 32);
            #pragma unroll
            for (int mi = 0; mi < 4; ++mi)
                #pragma unroll
                for (int nj = 0; nj < 4; ++nj) mma_bf16(acc[mi][nj], ah[mi], bl[nj]);
        }
        __syncthreads();

        if (cc == 7) {
            // ---- epilogue 1: t = acc + bd; spatial shift; rebuild A image ----
            // zero A hi+lo (boundary rows of the shift stay zero)
            #pragma unroll
            for (int i = tid; i < 8448; i += 512) ((float4*)smem)[i] = make_float4(0.f, 0.f, 0.f, 0.f);
            __syncthreads();

            const int grp = (w & 7) >> 1;        // shift group of this warp's columns
            #pragma unroll
            for (int nj = 0; nj < 4; ++nj) {
                const int C0 = n0 + 8 * nj + (lane & 3) * 2;
                const float2 bd2 = *(const float2*)(bd + C0);
                #pragma unroll
                for (int mi = 0; mi < 4; ++mi) {
                    #pragma unroll
                    for (int h = 0; h < 2; ++h) {
                        const int R = m0 + 16 * mi + (lane >> 2) + 8 * h;
                        const int r = R & 63;
                        int D; bool valid;
                        if      (grp == 0) { D = r - 1; valid = (r & 7) >= 1; }
                        else if (grp == 1) { D = r + 1; valid = (r & 7) <= 6; }
                        else if (grp == 2) { D = r - 8; valid = r >= 8; }
                        else               { D = r + 8; valid = r < 56; }
                        if (valid) {
                            float2 v;
                            v.x = acc[mi][nj][2 * h]     + bd2.x;
                            v.y = acc[mi][nj][2 * h + 1] + bd2.y;
                            __nv_bfloat162 h2 = __float22bfloat162_rn(v);
                            float2 rr;
                            rr.x = v.x - __bfloat162float(h2.x);
                            rr.y = v.y - __bfloat162float(h2.y);
                            __nv_bfloat162 l2 = __float22bfloat162_rn(rr);
                            const int row = (R & 64) + D;
                            *(uint32_t*)(smem + SM_AH + row * ASTRIDE + C0 * 2) = *(uint32_t*)&h2;
                            *(uint32_t*)(smem + SM_AL + row * ASTRIDE + C0 * 2) = *(uint32_t*)&l2;
                        }
                    }
                }
            }
            __syncthreads();
            #pragma unroll
            for (int mi = 0; mi < 4; ++mi)
                #pragma unroll
                for (int nj = 0; nj < 4; ++nj)
                    #pragma unroll
                    for (int q = 0; q < 4; ++q) acc[mi][nj][q] = 0.0f;
        }
    }

    // ---- epilogue 2: out = xe + up + bu (32B-sector-aligned float2 stores) ----
    #pragma unroll
    for (int nj = 0; nj < 4; ++nj) {
        const int C0 = n0 + 8 * nj + (lane & 3) * 2;
        const float2 bu2 = *(const float2*)(bu + C0);
        #pragma unroll
        for (int mi = 0; mi < 4; ++mi) {
            #pragma unroll
            for (int h = 0; h < 2; ++h) {
                const int R = m0 + 16 * mi + (lane >> 2) + 8 * h;
                const int r = R & 63;
                const int wsel = R >> 6;
                const float* xb = wsel ? xbB : xbA;
                const int wglob = 2 * blockIdx.x + wsel;
                const float2 xe = *(const float2*)(xb + (size_t)((r >> 3) * 64 + (r & 7)) * CDIM + C0);
                float2 o;
                o.x = acc[mi][nj][2 * h]     + bu2.x + xe.x;
                o.y = acc[mi][nj][2 * h + 1] + bu2.y + xe.y;
                *(float2*)(out + ((size_t)wglob * 64 + r) * CDIM + C0) = o;
            }
        }
    }
}

// ---------------- launcher ----------------
extern "C" void kernel_launch(void* const* d_in, const int* in_sizes, int n_in,
                              void* d_out, int out_size) {
    const float* z  = (const float*)d_in[0];
    const float* x  = (const float*)d_in[1];
    const float* Wd = (const float*)d_in[2];
    const float* bd = (const float*)d_in[3];
    const float* Wu = (const float*)d_in[4];
    const float* bu = (const float*)d_in[5];
    float* out = (float*)d_out;

    k_prepw<<<16, 256>>>(Wd, Wu);
    k_zmax<<<BATCH, 256>>>(z);
    k_sim<<<BATCH * NWIN, 256>>>(x);
    k_topk<<<BATCH, 64>>>();

    cudaFuncSetAttribute(k_main, cudaFuncAttributeMaxDynamicSharedMemorySize, SM_TOT);
    k_main<<<BATCH * TOPKN / 2, 512, SM_TOT>>>(x, bd, bu, out);
}

// round 9
// speedup vs baseline: 2.4784x; 1.1830x over previous
#include <cuda_runtime.h>
#include <cuda_bf16.h>
#include <cstdint>
#include <cstddef>

// Problem constants
#define BATCH 32
#define NT    256
#define NS    4096
#define CDIM  256
#define TOPKN 32
#define NWIN  64      // 8x8 windows of 8x8 tokens

// ---------------- device scratch ----------------
__device__ unsigned g_zmaxu[BATCH * CDIM];
__device__ float    g_simw[BATCH * NWIN];
__device__ int      g_idx[BATCH * TOPKN];
// tf32 fragment-ordered chunk images of Wd (cc 0..7) and Wu (cc 8..15):
// per chunk: [ntile 0..31][kstep 0..3][lane 0..31][2 regs] = 8192 words = 32KB
__device__ __align__(16) uint32_t g_Bt[16 * 8192];

// ---------------- asm helpers ----------------
__device__ __forceinline__ uint32_t s2u(const void* p) {
    uint32_t a;
    asm("{ .reg .u64 t; cvta.to.shared.u64 t, %1; cvt.u32.u64 %0, t; }"
        : "=r"(a) : "l"(p));
    return a;
}

__device__ __forceinline__ uint32_t cvt_tf32(float v) {
    uint32_t u;
    asm("cvt.rna.tf32.f32 %0, %1;" : "=r"(u) : "f"(v));
    return u;
}

__device__ __forceinline__ void st32(uint32_t addr, uint32_t v) {
    asm volatile("st.shared.b32 [%0], %1;" :: "r"(addr), "r"(v) : "memory");
}

__device__ __forceinline__ void lds128(uint32_t* r, uint32_t addr) {
    asm volatile("ld.shared.v4.b32 {%0,%1,%2,%3}, [%4];"
        : "=r"(r[0]), "=r"(r[1]), "=r"(r[2]), "=r"(r[3]) : "r"(addr));
}

__device__ __forceinline__ void lds64(uint32_t* r, uint32_t addr) {
    asm volatile("ld.shared.v2.b32 {%0,%1}, [%2];"
        : "=r"(r[0]), "=r"(r[1]) : "r"(addr));
}

__device__ __forceinline__ void mma_tf32(float* c, const uint32_t* a, const uint32_t* b) {
    asm volatile(
        "mma.sync.aligned.m16n8k8.row.col.f32.tf32.tf32.f32 "
        "{%0,%1,%2,%3}, {%4,%5,%6,%7}, {%8,%9}, {%0,%1,%2,%3};"
        : "+f"(c[0]), "+f"(c[1]), "+f"(c[2]), "+f"(c[3])
        : "r"(a[0]), "r"(a[1]), "r"(a[2]), "r"(a[3]), "r"(b[0]), "r"(b[1]));
}

__device__ __forceinline__ void cp16(uint32_t dst, const void* src) {
    asm volatile("cp.async.cg.shared.global [%0], [%1], 16;"
                 :: "r"(dst), "l"(src) : "memory");
}
#define CP_COMMIT() asm volatile("cp.async.commit_group;" ::: "memory")
#define CP_WAIT(n)  asm volatile("cp.async.wait_group %0;" :: "n"(n) : "memory")

// ordered-uint encoding for float atomicMax
__device__ __forceinline__ unsigned encf(float f) {
    unsigned u = __float_as_uint(f);
    return (u >> 31) ? ~u : (u | 0x80000000u);
}
__device__ __forceinline__ float decf(unsigned u) {
    return __uint_as_float((u >> 31) ? (u & 0x7fffffffu) : ~u);
}

// ---------------- K0: tf32 fragment-permute weights + init zmax ----------------
// grid 16 (= mat*8 + chunk), block 256: thread = output row n
__global__ void k_prepw(const float* __restrict__ Wd, const float* __restrict__ Wu) {
    const int cc = blockIdx.x;
    const float* W = (cc >> 3) ? Wu : Wd;
    const int n = threadIdx.x;
    const int nt = n >> 3, gg = n & 7;
    const int cbase = (cc & 7) * 32;
    uint32_t* dst = g_Bt + cc * 8192;
    #pragma unroll
    for (int kl = 0; kl < 32; ++kl) {
        const int ks = kl >> 3, kk = kl & 7;
        const int lane = gg * 4 + (kk & 3);
        const int reg = kk >> 2;
        dst[((nt * 4 + ks) * 32 + lane) * 2 + reg] = cvt_tf32(W[n * 256 + cbase + kl]);
    }
    // init zmax atomics (encoding 0 == -inf)
    const int gid = cc * 256 + n;
    g_zmaxu[gid] = 0u;
    g_zmaxu[gid + 4096] = 0u;
}

// ---------------- K1: z_max over Nt (parallel, atomic) ----------------
// grid 256 = 32 batches x 8 row groups
__global__ void k_zmax(const float* __restrict__ z) {
    const int b = blockIdx.x >> 3, rg = blockIdx.x & 7;
    const int c = threadIdx.x;
    const float* zb = z + ((size_t)b * NT + (size_t)rg * 32) * CDIM + c;
    float m = zb[0];
    #pragma unroll 8
    for (int n = 1; n < 32; ++n) m = fmaxf(m, zb[(size_t)n * CDIM]);
    atomicMax(&g_zmaxu[b * CDIM + c], encf(m));
}

// ---------------- K2: per-window mean similarity ----------------
__global__ void k_sim(const float* __restrict__ x) {
    const int bw = blockIdx.x;
    const int b = bw >> 6;
    const int win = bw & 63;
    const int wh = win >> 3, ww = win & 7;

    __shared__ float zm[CDIM];
    __shared__ float tok[64];

    const int tid = threadIdx.x;
    zm[tid] = decf(g_zmaxu[b * CDIM + tid]);
    __syncthreads();

    const int w = tid >> 5, l = tid & 31;
    const float* xb = x + ((size_t)b * NS + (size_t)wh * 512 + (size_t)ww * 8) * CDIM;
    const float4* zm4 = (const float4*)zm;
    const float4 z0 = zm4[2 * l];
    const float4 z1 = zm4[2 * l + 1];

    #pragma unroll
    for (int m = 0; m < 8; ++m) {
        const float4* row = (const float4*)(xb + (size_t)(w * 64 + m) * CDIM);
        const float4 v0 = row[2 * l];
        const float4 v1 = row[2 * l + 1];
        float a = v0.x * z0.x + v0.y * z0.y + v0.z * z0.z + v0.w * z0.w
                + v1.x * z1.x + v1.y * z1.y + v1.z * z1.z + v1.w * z1.w;
        #pragma unroll
        for (int off = 16; off; off >>= 1) a += __shfl_xor_sync(0xffffffffu, a, off);
        if (l == 0) tok[w * 8 + m] = a;
    }
    __syncthreads();
    if (tid < 32) {
        float v = tok[tid] + tok[tid + 32];
        #pragma unroll
        for (int off = 16; off; off >>= 1) v += __shfl_xor_sync(0xffffffffu, v, off);
        if (tid == 0) g_simw[b * NWIN + win] = v * (1.0f / (256.0f * 64.0f));
    }
}

// ---------------- K3: rank-based top-k (desc value, tie -> lower index) ----------------
__global__ void k_topk() {
    const int b = blockIdx.x;
    const int t = threadIdx.x;            // 64 threads
    __shared__ float v[NWIN];
    v[t] = g_simw[b * NWIN + t];
    __syncthreads();
    const float mv = v[t];
    int rank = 0;
    #pragma unroll
    for (int j = 0; j < NWIN; ++j) {
        const float vj = v[j];
        rank += (vj > mv) || (vj == mv && j < t);
    }
    if (rank < TOPKN) g_idx[b * TOPKN + rank] = t;
}

// ---------------- K4: fused tf32 mma.sync main ----------------
// SMEM (dynamic, bytes):
//   A_perm: [mt 0..7][kst 0..31][lane 0..31][4 regs], 528 B per (mt,kst) blk
//           = 8*32*528 = 135168                       @ 0
//   B buffers: 2 x 32768 (fragment-ordered chunk)     @ 135168
#define SM_A   0
#define SM_B   135168
#define SM_TOT 200704
#define ABLK   528

__global__ void __launch_bounds__(512, 1) k_main(const float* __restrict__ x,
                                                 const float* __restrict__ bd,
                                                 const float* __restrict__ bu,
                                                 float* __restrict__ out) {
    extern __shared__ uint8_t smem[];
    const uint32_t sb = s2u(smem);
    const int tid  = threadIdx.x;
    const int lane = tid & 31;
    const int w    = tid >> 5;            // warp 0..15
    const int m0   = (w >> 3) * 64;       // warp M base (0 or 64)
    const int n0   = (w & 7) * 32;        // warp N base
    const int g    = lane >> 2, tig = lane & 3;

    // prefetch B chunk 0
    {
        const uint8_t* src = (const uint8_t*)g_Bt;
        const uint32_t dst = sb + SM_B;
        #pragma unroll
        for (int i = 0; i < 4; ++i) cp16(dst + (tid + 512 * i) * 16, src + (tid + 512 * i) * 16);
        CP_COMMIT();
    }

    // window bases
    const int w0g = 2 * blockIdx.x, w1g = w0g + 1;
    const int winA = g_idx[(w0g >> 5) * TOPKN + (w0g & 31)];
    const int winB = g_idx[(w1g >> 5) * TOPKN + (w1g & 31)];
    const float* xbA = x + ((size_t)(w0g >> 5) * NS + (size_t)(winA >> 3) * 512 + (size_t)(winA & 7) * 8) * CDIM;
    const float* xbB = x + ((size_t)(w1g >> 5) * NS + (size_t)(winB >> 3) * 512 + (size_t)(winB & 7) * 8) * CDIM;

    // ---- gather xe (128 rows x 256 ch) into fragment-ordered tf32 A_perm ----
    #pragma unroll 1
    for (int i = 0; i < 16; ++i) {
        const int idx = tid + 512 * i;
        const int row = idx >> 6, cg = idx & 63, c0 = cg * 4;
        const int r = row & 63;
        const float* xb = (row < 64) ? xbA : xbB;
        const float4 v = *(const float4*)(xb + (size_t)((r >> 3) * 64 + (r & 7)) * CDIM + c0);
        const int mt = row >> 4, kst = c0 >> 3;
        const int reg = ((c0 >> 2) & 1) * 2 + ((row >> 3) & 1);
        const uint32_t base = sb + SM_A + (uint32_t)(mt * 32 + kst) * ABLK
                            + (uint32_t)((row & 7) * 4) * 16 + (uint32_t)reg * 4;
        st32(base +  0, cvt_tf32(v.x));
        st32(base + 16, cvt_tf32(v.y));
        st32(base + 32, cvt_tf32(v.z));
        st32(base + 48, cvt_tf32(v.w));
    }
    __syncthreads();

    // hot-loop bases
    const uint32_t aBase = sb + SM_A + (uint32_t)((w >> 3) * 4 * 32) * ABLK + (uint32_t)lane * 16;
    const uint32_t bBase = sb + SM_B + (uint32_t)((w & 7) * 4) * 1024 + (uint32_t)lane * 8;

    float acc[4][4][4];
    #pragma unroll
    for (int mi = 0; mi < 4; ++mi)
        #pragma unroll
        for (int nj = 0; nj < 4; ++nj)
            #pragma unroll
            for (int q = 0; q < 4; ++q) acc[mi][nj][q] = 0.0f;

    // ---- 16 k32-chunk stream: cc 0..7 = GEMM1 (Wd), 8..15 = GEMM2 (Wu) ----
    #pragma unroll 1
    for (int cc = 0; cc < 16; ++cc) {
        if (cc < 15) {
            const uint8_t* src = (const uint8_t*)g_Bt + (size_t)(cc + 1) * 32768;
            const uint32_t dst = sb + SM_B + (uint32_t)((cc + 1) & 1) * 32768;
            #pragma unroll
            for (int i = 0; i < 4; ++i) cp16(dst + (tid + 512 * i) * 16, src + (tid + 512 * i) * 16);
            CP_COMMIT();
            CP_WAIT(1);
        } else {
            CP_WAIT(0);
        }
        __syncthreads();

        const uint32_t aCk = aBase + (uint32_t)((cc & 7) * 4) * ABLK;
        const uint32_t bCk = bBase + (uint32_t)(cc & 1) * 32768;

        #pragma unroll
        for (int ks = 0; ks < 4; ++ks) {
            uint32_t a[4][4], b[4][2];
            #pragma unroll
            for (int mi = 0; mi < 4; ++mi)
                lds128(a[mi], aCk + (uint32_t)mi * (32 * ABLK) + (uint32_t)ks * ABLK);
            #pragma unroll
            for (int nj = 0; nj < 4; ++nj)
                lds64(b[nj], bCk + (uint32_t)nj * 1024 + (uint32_t)ks * 256);
            #pragma unroll
            for (int mi = 0; mi < 4; ++mi)
                #pragma unroll
                for (int nj = 0; nj < 4; ++nj) mma_tf32(acc[mi][nj], a[mi], b[nj]);
        }
        __syncthreads();

        if (cc == 7) {
            // ---- epilogue 1: t = acc + bd; spatial shift; rebuild A_perm ----
            const float4 z4 = make_float4(0.f, 0.f, 0.f, 0.f);
            #pragma unroll 1
            for (int i = tid; i < 8448; i += 512) ((float4*)smem)[i] = z4;
            __syncthreads();

            const int grp = (w & 7) >> 1;    // shift group of this warp's columns
            #pragma unroll
            for (int nj = 0; nj < 4; ++nj) {
                #pragma unroll
                for (int j = 0; j < 2; ++j) {
                    const int c = n0 + 8 * nj + 2 * tig + j;
                    const float bdv = __ldg(bd + c);
                    const int kst = c >> 3;
                    const int pr  = (c >> 2) & 1;
                    const int sl  = c & 3;
                    #pragma unroll
                    for (int mi = 0; mi < 4; ++mi) {
                        #pragma unroll
                        for (int h = 0; h < 2; ++h) {
                            const int R = m0 + 16 * mi + g + 8 * h;
                            const int r = R & 63;
                            int D; bool valid;
                            if      (grp == 0) { D = r - 1; valid = (r & 7) >= 1; }
                            else if (grp == 1) { D = r + 1; valid = (r & 7) <= 6; }
                            else if (grp == 2) { D = r - 8; valid = r >= 8; }
                            else               { D = r + 8; valid = r < 56; }
                            if (valid) {
                                const float t = acc[mi][nj][2 * h + j] + bdv;
                                const int Drow = (R & 64) + D;
                                const int mtD = Drow >> 4, rb = (Drow >> 3) & 1;
                                const int s = (Drow & 7) * 4 + sl;
                                const uint32_t addr = sb + SM_A
                                    + (uint32_t)(mtD * 32 + kst) * ABLK
                                    + (uint32_t)s * 16 + (uint32_t)(pr * 2 + rb) * 4;
                                st32(addr, cvt_tf32(t));
                            }
                        }
                    }
                }
            }
            __syncthreads();
            #pragma unroll
            for (int mi = 0; mi < 4; ++mi)
                #pragma unroll
                for (int nj = 0; nj < 4; ++nj)
                    #pragma unroll
                    for (int q = 0; q < 4; ++q) acc[mi][nj][q] = 0.0f;
        }
    }

    // ---- epilogue 2: out = xe + up + bu ----
    #pragma unroll
    for (int nj = 0; nj < 4; ++nj) {
        const int C0 = n0 + 8 * nj + 2 * tig;
        const float2 bu2 = *(const float2*)(bu + C0);
        #pragma unroll
        for (int mi = 0; mi < 4; ++mi) {
            #pragma unroll
            for (int h = 0; h < 2; ++h) {
                const int R = m0 + 16 * mi + g + 8 * h;
                const int r = R & 63;
                const int wsel = R >> 6;
                const float* xb = wsel ? xbB : xbA;
                const int wglob = 2 * blockIdx.x + wsel;
                const float2 xe = *(const float2*)(xb + (size_t)((r >> 3) * 64 + (r & 7)) * CDIM + C0);
                float2 o;
                o.x = acc[mi][nj][2 * h]     + bu2.x + xe.x;
                o.y = acc[mi][nj][2 * h + 1] + bu2.y + xe.y;
                *(float2*)(out + ((size_t)wglob * 64 + r) * CDIM + C0) = o;
            }
        }
    }
}

// ---------------- launcher ----------------
extern "C" void kernel_launch(void* const* d_in, const int* in_sizes, int n_in,
                              void* d_out, int out_size) {
    const float* z  = (const float*)d_in[0];
    const float* x  = (const float*)d_in[1];
    const float* Wd = (const float*)d_in[2];
    const float* bd = (const float*)d_in[3];
    const float* Wu = (const float*)d_in[4];
    const float* bu = (const float*)d_in[5];
    float* out = (float*)d_out;

    k_prepw<<<16, 256>>>(Wd, Wu);
    k_zmax<<<256, 256>>>(z);
    k_sim<<<BATCH * NWIN, 256>>>(x);
    k_topk<<<BATCH, 64>>>();

    cudaFuncSetAttribute(k_main, cudaFuncAttributeMaxDynamicSharedMemorySize, SM_TOT);
    k_main<<<BATCH * TOPKN / 2, 512, SM_TOT>>>(x, bd, bu, out);
}

// round 10
// speedup vs baseline: 2.7360x; 1.1039x over previous
#include <cuda_runtime.h>
#include <cuda_bf16.h>
#include <cstdint>
#include <cstddef>

// Problem constants
#define BATCH 32
#define NT    256
#define NS    4096
#define CDIM  256
#define TOPKN 32
#define NWIN  64      // 8x8 windows of 8x8 tokens

// ---------------- device scratch ----------------
__device__ unsigned g_zmaxu[BATCH * CDIM];
__device__ float    g_simw[BATCH * NWIN];
__device__ int      g_idx[BATCH * TOPKN];
// tf32 fragment-ordered B stages: 32 stages (gm(2) x chunk(8) x half(2)) x 16KB.
// Stage layout: [kstep_local 0..1][ntile 0..31][lane 0..31][2 regs] words.
__device__ __align__(16) uint32_t g_Bt[32 * 4096];

// ---------------- asm helpers ----------------
__device__ __forceinline__ uint32_t s2u(const void* p) {
    uint32_t a;
    asm("{ .reg .u64 t; cvta.to.shared.u64 t, %1; cvt.u32.u64 %0, t; }"
        : "=r"(a) : "l"(p));
    return a;
}

__device__ __forceinline__ uint32_t cvt_tf32(float v) {
    uint32_t u;
    asm("cvt.rna.tf32.f32 %0, %1;" : "=r"(u) : "f"(v));
    return u;
}

__device__ __forceinline__ void st32(uint32_t addr, uint32_t v) {
    asm volatile("st.shared.b32 [%0], %1;" :: "r"(addr), "r"(v) : "memory");
}

__device__ __forceinline__ void lds128(uint32_t* r, uint32_t addr) {
    asm volatile("ld.shared.v4.b32 {%0,%1,%2,%3}, [%4];"
        : "=r"(r[0]), "=r"(r[1]), "=r"(r[2]), "=r"(r[3]) : "r"(addr));
}

__device__ __forceinline__ void lds64(uint32_t* r, uint32_t addr) {
    asm volatile("ld.shared.v2.b32 {%0,%1}, [%2];"
        : "=r"(r[0]), "=r"(r[1]) : "r"(addr));
}

__device__ __forceinline__ void mma_tf32(float* c, const uint32_t* a, const uint32_t* b) {
    asm volatile(
        "mma.sync.aligned.m16n8k8.row.col.f32.tf32.tf32.f32 "
        "{%0,%1,%2,%3}, {%4,%5,%6,%7}, {%8,%9}, {%0,%1,%2,%3};"
        : "+f"(c[0]), "+f"(c[1]), "+f"(c[2]), "+f"(c[3])
        : "r"(a[0]), "r"(a[1]), "r"(a[2]), "r"(a[3]), "r"(b[0]), "r"(b[1]));
}

__device__ __forceinline__ void cp16(uint32_t dst, const void* src) {
    asm volatile("cp.async.cg.shared.global [%0], [%1], 16;"
                 :: "r"(dst), "l"(src) : "memory");
}
#define CP_COMMIT() asm volatile("cp.async.commit_group;" ::: "memory")
#define CP_WAIT(n)  asm volatile("cp.async.wait_group %0;" :: "n"(n) : "memory")

// ordered-uint encoding for float atomicMax
__device__ __forceinline__ unsigned encf(float f) {
    unsigned u = __float_as_uint(f);
    return (u >> 31) ? ~u : (u | 0x80000000u);
}
__device__ __forceinline__ float decf(unsigned u) {
    return __uint_as_float((u >> 31) ? (u & 0x7fffffffu) : ~u);
}

// ---------------- K0: tf32 fragment-permute weights (stage order) + init zmax ----------------
// grid 16 (= mat*8 + chunk), block 256: thread = output row n
__global__ void k_prepw(const float* __restrict__ Wd, const float* __restrict__ Wu) {
    const int blk = blockIdx.x;              // gm*8 + cc
    const float* W = (blk >> 3) ? Wu : Wd;
    const int n = threadIdx.x;
    const int nt = n >> 3, gg = n & 7;
    const int cbase = (blk & 7) * 32;
    uint32_t* dst = g_Bt + blk * 8192;       // 2 stages of 4096 words
    #pragma unroll
    for (int kl = 0; kl < 32; ++kl) {
        const int ks = kl >> 3;              // kstep 0..3 within chunk
        const int hh = ks >> 1;              // stage half
        const int kloc = ks & 1;
        const int kk = kl & 7;
        const int lane = gg * 4 + (kk & 3);
        const int reg = kk >> 2;
        dst[hh * 4096 + kloc * 2048 + nt * 64 + lane * 2 + reg] =
            cvt_tf32(W[n * 256 + cbase + kl]);
    }
    // init zmax atomics (encoding 0 == -inf)
    const int gid = blk * 256 + n;
    g_zmaxu[gid] = 0u;
    g_zmaxu[gid + 4096] = 0u;
}

// ---------------- K1: z_max over Nt (parallel, atomic) ----------------
__global__ void k_zmax(const float* __restrict__ z) {
    const int b = blockIdx.x >> 3, rg = blockIdx.x & 7;
    const int c = threadIdx.x;
    const float* zb = z + ((size_t)b * NT + (size_t)rg * 32) * CDIM + c;
    float m = zb[0];
    #pragma unroll 8
    for (int n = 1; n < 32; ++n) m = fmaxf(m, zb[(size_t)n * CDIM]);
    atomicMax(&g_zmaxu[b * CDIM + c], encf(m));
}

// ---------------- K2: per-window mean similarity ----------------
__global__ void k_sim(const float* __restrict__ x) {
    const int bw = blockIdx.x;
    const int b = bw >> 6;
    const int win = bw & 63;
    const int wh = win >> 3, ww = win & 7;

    __shared__ float zm[CDIM];
    __shared__ float tok[64];

    const int tid = threadIdx.x;
    zm[tid] = decf(g_zmaxu[b * CDIM + tid]);
    __syncthreads();

    const int w = tid >> 5, l = tid & 31;
    const float* xb = x + ((size_t)b * NS + (size_t)wh * 512 + (size_t)ww * 8) * CDIM;
    const float4* zm4 = (const float4*)zm;
    const float4 z0 = zm4[2 * l];
    const float4 z1 = zm4[2 * l + 1];

    #pragma unroll
    for (int m = 0; m < 8; ++m) {
        const float4* row = (const float4*)(xb + (size_t)(w * 64 + m) * CDIM);
        const float4 v0 = row[2 * l];
        const float4 v1 = row[2 * l + 1];
        float a = v0.x * z0.x + v0.y * z0.y + v0.z * z0.z + v0.w * z0.w
                + v1.x * z1.x + v1.y * z1.y + v1.z * z1.z + v1.w * z1.w;
        #pragma unroll
        for (int off = 16; off; off >>= 1) a += __shfl_xor_sync(0xffffffffu, a, off);
        if (l == 0) tok[w * 8 + m] = a;
    }
    __syncthreads();
    if (tid < 32) {
        float v = tok[tid] + tok[tid + 32];
        #pragma unroll
        for (int off = 16; off; off >>= 1) v += __shfl_xor_sync(0xffffffffu, v, off);
        if (tid == 0) g_simw[b * NWIN + win] = v * (1.0f / (256.0f * 64.0f));
    }
}

// ---------------- K3: rank-based top-k (desc value, tie -> lower index) ----------------
__global__ void k_topk() {
    const int b = blockIdx.x;
    const int t = threadIdx.x;            // 64 threads
    __shared__ float v[NWIN];
    v[t] = g_simw[b * NWIN + t];
    __syncthreads();
    const float mv = v[t];
    int rank = 0;
    #pragma unroll
    for (int j = 0; j < NWIN; ++j) {
        const float vj = v[j];
        rank += (vj > mv) || (vj == mv && j < t);
    }
    if (rank < TOPKN) g_idx[b * TOPKN + rank] = t;
}

// ---------------- K4: fused tf32 mma.sync main (1 window/CTA, 2 CTAs/SM) ----------------
// SMEM (dynamic, bytes):
//   A_perm: [mt 0..3][kst 0..31][lane slots], 528 B per (mt,kst) blk = 67584 @ 0
//   B ring: 2 x 16384 (one stage = 2 ksteps, fragment-ordered)        @ 67584
#define SM_A   0
#define SM_B   67584
#define SM_TOT 100352
#define ABLK   528

__global__ void __launch_bounds__(256, 2) k_main(const float* __restrict__ x,
                                                 const float* __restrict__ bd,
                                                 const float* __restrict__ bu,
                                                 float* __restrict__ out) {
    extern __shared__ uint8_t smem[];
    const uint32_t sb = s2u(smem);
    const int tid  = threadIdx.x;
    const int lane = tid & 31;
    const int w    = tid >> 5;            // warp 0..7
    const int n0   = w * 32;              // warp N base (M covers all 64 rows)
    const int g    = lane >> 2, tig = lane & 3;

    // prefetch B stage 0 (16KB)
    {
        const uint8_t* src = (const uint8_t*)g_Bt;
        const uint32_t dst = sb + SM_B;
        #pragma unroll
        for (int i = 0; i < 4; ++i) cp16(dst + (tid + 256 * i) * 16, src + (tid + 256 * i) * 16);
        CP_COMMIT();
    }

    // window base
    const int wg = blockIdx.x;
    const int win = g_idx[(wg >> 5) * TOPKN + (wg & 31)];
    const float* xb = x + ((size_t)(wg >> 5) * NS + (size_t)(win >> 3) * 512 + (size_t)(win & 7) * 8) * CDIM;

    // ---- gather xe (64 rows x 256 ch) into fragment-ordered tf32 A_perm ----
    #pragma unroll 1
    for (int i = 0; i < 16; ++i) {
        const int idx = tid + 256 * i;
        const int row = idx >> 6, c0 = (idx & 63) * 4;
        const float4 v = *(const float4*)(xb + (size_t)((row >> 3) * 64 + (row & 7)) * CDIM + c0);
        const int mt = row >> 4, kst = c0 >> 3;
        const int reg = ((c0 >> 2) & 1) * 2 + ((row >> 3) & 1);
        const uint32_t base = sb + SM_A + (uint32_t)(mt * 32 + kst) * ABLK
                            + (uint32_t)((row & 7) * 4) * 16 + (uint32_t)reg * 4;
        st32(base +  0, cvt_tf32(v.x));
        st32(base + 16, cvt_tf32(v.y));
        st32(base + 32, cvt_tf32(v.z));
        st32(base + 48, cvt_tf32(v.w));
    }
    __syncthreads();

    const uint32_t aBase = sb + SM_A + (uint32_t)lane * 16;
    const uint32_t bBase = sb + SM_B + (uint32_t)lane * 8 + (uint32_t)(w * 4) * 256;

    float acc[4][4][4];
    #pragma unroll
    for (int mi = 0; mi < 4; ++mi)
        #pragma unroll
        for (int nj = 0; nj < 4; ++nj)
            #pragma unroll
            for (int q = 0; q < 4; ++q) acc[mi][nj][q] = 0.0f;

    // ---- 32-stage stream: ss 0..15 = GEMM1 (Wd), 16..31 = GEMM2 (Wu) ----
    #pragma unroll 1
    for (int ss = 0; ss < 32; ++ss) {
        if (ss < 31) {
            __syncthreads();   // all warps done reading the buffer we overwrite
            const uint8_t* src = (const uint8_t*)g_Bt + (size_t)(ss + 1) * 16384;
            const uint32_t dst = sb + SM_B + (uint32_t)((ss + 1) & 1) * 16384;
            #pragma unroll
            for (int i = 0; i < 4; ++i) cp16(dst + (tid + 256 * i) * 16, src + (tid + 256 * i) * 16);
            CP_COMMIT();
            CP_WAIT(1);        // stage ss landed
        } else {
            CP_WAIT(0);
        }
        __syncthreads();

        const uint32_t bufB = bBase + (uint32_t)(ss & 1) * 16384;
        const int cc = (ss >> 1) & 7, hh = ss & 1;

        #pragma unroll
        for (int kl = 0; kl < 2; ++kl) {
            const int kg = cc * 4 + hh * 2 + kl;
            uint32_t a[4][4], b[4][2];
            #pragma unroll
            for (int mi = 0; mi < 4; ++mi)
                lds128(a[mi], aBase + (uint32_t)(mi * 32 + kg) * ABLK);
            #pragma unroll
            for (int nj = 0; nj < 4; ++nj)
                lds64(b[nj], bufB + (uint32_t)nj * 256 + (uint32_t)kl * 8192);
            #pragma unroll
            for (int mi = 0; mi < 4; ++mi)
                #pragma unroll
                for (int nj = 0; nj < 4; ++nj) mma_tf32(acc[mi][nj], a[mi], b[nj]);
        }

        if (ss == 15) {
            // ---- epilogue 1: t = acc + bd; spatial shift; rebuild A_perm ----
            __syncthreads();   // all GEMM1 A reads complete
            const float4 z4 = make_float4(0.f, 0.f, 0.f, 0.f);
            #pragma unroll 1
            for (int i = tid; i < 4224; i += 256) ((float4*)smem)[i] = z4;
            __syncthreads();

            const int grp = w >> 1;          // shift group of this warp's columns
            #pragma unroll
            for (int nj = 0; nj < 4; ++nj) {
                #pragma unroll
                for (int j = 0; j < 2; ++j) {
                    const int c = n0 + 8 * nj + 2 * tig + j;
                    const float bdv = __ldg(bd + c);
                    const int kst = c >> 3;
                    const int pr  = (c >> 2) & 1;
                    const int sl  = c & 3;
                    #pragma unroll
                    for (int mi = 0; mi < 4; ++mi) {
                        #pragma unroll
                        for (int h = 0; h < 2; ++h) {
                            const int r = 16 * mi + g + 8 * h;
                            int D; bool valid;
                            if      (grp == 0) { D = r - 1; valid = (r & 7) >= 1; }
                            else if (grp == 1) { D = r + 1; valid = (r & 7) <= 6; }
                            else if (grp == 2) { D = r - 8; valid = r >= 8; }
                            else               { D = r + 8; valid = r < 56; }
                            if (valid) {
                                const float t = acc[mi][nj][2 * h + j] + bdv;
                                const int mtD = D >> 4, rb = (D >> 3) & 1;
                                const int s = (D & 7) * 4 + sl;
                                const uint32_t addr = sb + SM_A
                                    + (uint32_t)(mtD * 32 + kst) * ABLK
                                    + (uint32_t)s * 16 + (uint32_t)(pr * 2 + rb) * 4;
                                st32(addr, cvt_tf32(t));
                            }
                        }
                    }
                }
            }
            // next iteration's two barriers order the scatter before GEMM2 reads
            #pragma unroll
            for (int mi = 0; mi < 4; ++mi)
                #pragma unroll
                for (int nj = 0; nj < 4; ++nj)
                    #pragma unroll
                    for (int q = 0; q < 4; ++q) acc[mi][nj][q] = 0.0f;
        }
    }

    // ---- epilogue 2: out = xe + up + bu ----
    #pragma unroll
    for (int nj = 0; nj < 4; ++nj) {
        const int C0 = n0 + 8 * nj + 2 * tig;
        const float2 bu2 = *(const float2*)(bu + C0);
        #pragma unroll
        for (int mi = 0; mi < 4; ++mi) {
            #pragma unroll
            for (int h = 0; h < 2; ++h) {
                const int r = 16 * mi + g + 8 * h;
                const float2 xe = *(const float2*)(xb + (size_t)((r >> 3) * 64 + (r & 7)) * CDIM + C0);
                float2 o;
                o.x = acc[mi][nj][2 * h]     + bu2.x + xe.x;
                o.y = acc[mi][nj][2 * h + 1] + bu2.y + xe.y;
                *(float2*)(out + ((size_t)wg * 64 + r) * CDIM + C0) = o;
            }
        }
    }
}

// ---------------- launcher ----------------
extern "C" void kernel_launch(void* const* d_in, const int* in_sizes, int n_in,
                              void* d_out, int out_size) {
    const float* z  = (const float*)d_in[0];
    const float* x  = (const float*)d_in[1];
    const float* Wd = (const float*)d_in[2];
    const float* bd = (const float*)d_in[3];
    const float* Wu = (const float*)d_in[4];
    const float* bu = (const float*)d_in[5];
    float* out = (float*)d_out;

    k_prepw<<<16, 256>>>(Wd, Wu);
    k_zmax<<<256, 256>>>(z);
    k_sim<<<BATCH * NWIN, 256>>>(x);
    k_topk<<<BATCH, 64>>>();

    cudaFuncSetAttribute(k_main, cudaFuncAttributeMaxDynamicSharedMemorySize, SM_TOT);
    k_main<<<BATCH * TOPKN, 256, SM_TOT>>>(x, bd, bu, out);
}

// round 12
// speedup vs baseline: 2.9378x; 1.0738x over previous
#include <cuda_runtime.h>
#include <cuda_bf16.h>
#include <cstdint>
#include <cstddef>

// Problem constants
#define BATCH 32
#define NT    256
#define NS    4096
#define CDIM  256
#define TOPKN 32
#define NWIN  64      // 8x8 windows of 8x8 tokens

// ---------------- device scratch ----------------
__device__ unsigned g_zmaxu[BATCH * CDIM];
__device__ float    g_simw[BATCH * NWIN];
__device__ int      g_idx[BATCH * TOPKN];
// tf32 fragment-ordered B, linear in global kstep kv (0..63; kv>=32 -> Wu):
// word offset = kv*2048 + ntile*64 + lane*2 + reg   (512KB total, L2-resident)
__device__ __align__(16) uint32_t g_Bt[64 * 2048];

// ---------------- asm helpers ----------------
__device__ __forceinline__ uint32_t s2u(const void* p) {
    uint32_t a;
    asm("{ .reg .u64 t; cvta.to.shared.u64 t, %1; cvt.u32.u64 %0, t; }"
        : "=r"(a) : "l"(p));
    return a;
}

__device__ __forceinline__ uint32_t cvt_tf32(float v) {
    uint32_t u;
    asm("cvt.rna.tf32.f32 %0, %1;" : "=r"(u) : "f"(v));
    return u;
}

__device__ __forceinline__ void st32(uint32_t addr, uint32_t v) {
    asm volatile("st.shared.b32 [%0], %1;" :: "r"(addr), "r"(v) : "memory");
}

__device__ __forceinline__ void lds128(uint32_t* r, uint32_t addr) {
    asm volatile("ld.shared.v4.b32 {%0,%1,%2,%3}, [%4];"
        : "=r"(r[0]), "=r"(r[1]), "=r"(r[2]), "=r"(r[3]) : "r"(addr));
}

__device__ __forceinline__ void mma_tf32(float* c, const uint32_t* a, const uint32_t* b) {
    asm volatile(
        "mma.sync.aligned.m16n8k8.row.col.f32.tf32.tf32.f32 "
        "{%0,%1,%2,%3}, {%4,%5,%6,%7}, {%8,%9}, {%0,%1,%2,%3};"
        : "+f"(c[0]), "+f"(c[1]), "+f"(c[2]), "+f"(c[3])
        : "r"(a[0]), "r"(a[1]), "r"(a[2]), "r"(a[3]), "r"(b[0]), "r"(b[1]));
}

// ordered-uint encoding for float atomicMax
__device__ __forceinline__ unsigned encf(float f) {
    unsigned u = __float_as_uint(f);
    return (u >> 31) ? ~u : (u | 0x80000000u);
}
__device__ __forceinline__ float decf(unsigned u) {
    return __uint_as_float((u >> 31) ? (u & 0x7fffffffu) : ~u);
}

// ---------------- K0: tf32 fragment-permute weights + init zmax ----------------
// grid 16 (= mat*8 + chunk), block 256: thread = output row n
__global__ void k_prepw(const float* __restrict__ Wd, const float* __restrict__ Wu) {
    const int blk = blockIdx.x;              // gm*8 + c
    const int gm = blk >> 3, c = blk & 7;
    const float* W = gm ? Wu : Wd;
    const int n = threadIdx.x;
    const int nt = n >> 3, gg = n & 7;
    const int cbase = c * 32;
    #pragma unroll
    for (int kl = 0; kl < 32; ++kl) {
        const int ks = kl >> 3;              // kstep within this 32-k chunk
        const int kk = kl & 7;
        const int lane = gg * 4 + (kk & 3);
        const int reg = kk >> 2;
        const int kv = gm * 32 + c * 4 + ks; // global kstep
        g_Bt[(size_t)kv * 2048 + nt * 64 + lane * 2 + reg] =
            cvt_tf32(W[n * 256 + cbase + kl]);
    }
    // init zmax atomics (encoding 0 == -inf)
    const int gid = blk * 256 + n;
    g_zmaxu[gid] = 0u;
    g_zmaxu[gid + 4096] = 0u;
}

// ---------------- K1: z_max over Nt (parallel, atomic) ----------------
__global__ void k_zmax(const float* __restrict__ z) {
    const int b = blockIdx.x >> 3, rg = blockIdx.x & 7;
    const int c = threadIdx.x;
    const float* zb = z + ((size_t)b * NT + (size_t)rg * 32) * CDIM + c;
    float m = zb[0];
    #pragma unroll 8
    for (int n = 1; n < 32; ++n) m = fmaxf(m, zb[(size_t)n * CDIM]);
    atomicMax(&g_zmaxu[b * CDIM + c], encf(m));
}

// ---------------- K2: per-window mean similarity ----------------
__global__ void k_sim(const float* __restrict__ x) {
    const int bw = blockIdx.x;
    const int b = bw >> 6;
    const int win = bw & 63;
    const int wh = win >> 3, ww = win & 7;

    __shared__ float zm[CDIM];
    __shared__ float tok[64];

    const int tid = threadIdx.x;
    zm[tid] = decf(g_zmaxu[b * CDIM + tid]);
    __syncthreads();

    const int w = tid >> 5, l = tid & 31;
    const float* xb = x + ((size_t)b * NS + (size_t)wh * 512 + (size_t)ww * 8) * CDIM;
    const float4* zm4 = (const float4*)zm;
    const float4 z0 = zm4[2 * l];
    const float4 z1 = zm4[2 * l + 1];

    #pragma unroll
    for (int m = 0; m < 8; ++m) {
        const float4* row = (const float4*)(xb + (size_t)(w * 64 + m) * CDIM);
        const float4 v0 = row[2 * l];
        const float4 v1 = row[2 * l + 1];
        float a = v0.x * z0.x + v0.y * z0.y + v0.z * z0.z + v0.w * z0.w
                + v1.x * z1.x + v1.y * z1.y + v1.z * z1.z + v1.w * z1.w;
        #pragma unroll
        for (int off = 16; off; off >>= 1) a += __shfl_xor_sync(0xffffffffu, a, off);
        if (l == 0) tok[w * 8 + m] = a;
    }
    __syncthreads();
    if (tid < 32) {
        float v = tok[tid] + tok[tid + 32];
        #pragma unroll
        for (int off = 16; off; off >>= 1) v += __shfl_xor_sync(0xffffffffu, v, off);
        if (tid == 0) g_simw[b * NWIN + win] = v * (1.0f / (256.0f * 64.0f));
    }
}

// ---------------- K3: rank-based top-k (desc value, tie -> lower index) ----------------
__global__ void k_topk() {
    const int b = blockIdx.x;
    const int t = threadIdx.x;            // 64 threads
    __shared__ float v[NWIN];
    v[t] = g_simw[b * NWIN + t];
    __syncthreads();
    const float mv = v[t];
    int rank = 0;
    #pragma unroll
    for (int j = 0; j < NWIN; ++j) {
        const float vj = v[j];
        rank += (vj > mv) || (vj == mv && j < t);
    }
    if (rank < TOPKN) g_idx[b * TOPKN + rank] = t;
}

// ---------------- K4: fused tf32 mma.sync main (B straight from L2) ----------------
// SMEM (dynamic): A_perm only: [mt 0..3][kst 0..31] blocks of 528 B = 67584
#define SM_TOT 67584
#define ABLK   528

__global__ void __launch_bounds__(256, 2) k_main(const float* __restrict__ x,
                                                 const float* __restrict__ bd,
                                                 const float* __restrict__ bu,
                                                 float* __restrict__ out) {
    extern __shared__ uint8_t smem[];
    const uint32_t sb = s2u(smem);
    const int tid  = threadIdx.x;
    const int lane = tid & 31;
    const int w    = tid >> 5;            // warp 0..7
    const int n0   = w * 32;              // warp N base
    const int g    = lane >> 2, tig = lane & 3;

    // window base
    const int wg = blockIdx.x;
    const int win = g_idx[(wg >> 5) * TOPKN + (wg & 31)];
    const float* xb = x + ((size_t)(wg >> 5) * NS + (size_t)(win >> 3) * 512 + (size_t)(win & 7) * 8) * CDIM;

    // ---- gather xe (64 rows x 256 ch) into fragment-ordered tf32 A_perm ----
    #pragma unroll 1
    for (int i = 0; i < 16; ++i) {
        const int idx = tid + 256 * i;
        const int row = idx >> 6, c0 = (idx & 63) * 4;
        const float4 v = *(const float4*)(xb + (size_t)((row >> 3) * 64 + (row & 7)) * CDIM + c0);
        const int mt = row >> 4, kst = c0 >> 3;
        const int reg = ((c0 >> 2) & 1) * 2 + ((row >> 3) & 1);
        const uint32_t base = sb + (uint32_t)(mt * 32 + kst) * ABLK
                            + (uint32_t)((row & 7) * 4) * 16 + (uint32_t)reg * 4;
        st32(base +  0, cvt_tf32(v.x));
        st32(base + 16, cvt_tf32(v.y));
        st32(base + 32, cvt_tf32(v.z));
        st32(base + 48, cvt_tf32(v.w));
    }
    __syncthreads();

    const uint32_t aBase = sb + (uint32_t)lane * 16;
    const uint32_t* bp = g_Bt + (size_t)(w * 4) * 64 + (size_t)lane * 2;

    float acc[4][4][4];
    #pragma unroll
    for (int mi = 0; mi < 4; ++mi)
        #pragma unroll
        for (int nj = 0; nj < 4; ++nj)
            #pragma unroll
            for (int q = 0; q < 4; ++q) acc[mi][nj][q] = 0.0f;

    // B fragment double buffer; prefetch kv=0
    uint2 bn[2][4];
    #pragma unroll
    for (int nj = 0; nj < 4; ++nj)
        bn[0][nj] = __ldg((const uint2*)(bp + (size_t)nj * 64));

    // ---- 64 ksteps: kv 0..31 = GEMM1 (Wd), 32..63 = GEMM2 (Wu) ----
    #pragma unroll 1
    for (int gm = 0; gm < 2; ++gm) {
        #pragma unroll 2
        for (int kg = 0; kg < 32; ++kg) {
            const int kv  = gm * 32 + kg;
            const int cur = kv & 1;
            const int kvn = (kv < 63) ? (kv + 1) : 63;
            #pragma unroll
            for (int nj = 0; nj < 4; ++nj)
                bn[cur ^ 1][nj] = __ldg((const uint2*)(bp + (size_t)kvn * 2048 + (size_t)nj * 64));
            uint32_t a[4][4];
            #pragma unroll
            for (int mi = 0; mi < 4; ++mi)
                lds128(a[mi], aBase + (uint32_t)(mi * 32 + kg) * ABLK);
            #pragma unroll
            for (int mi = 0; mi < 4; ++mi)
                #pragma unroll
                for (int nj = 0; nj < 4; ++nj)
                    mma_tf32(acc[mi][nj], a[mi], (const uint32_t*)&bn[cur][nj]);
        }

        if (gm == 0) {
            // ---- epilogue 1: t = acc + bd; spatial shift; rebuild A_perm ----
            __syncthreads();   // all warps done reading A for GEMM1
            const float4 z4 = make_float4(0.f, 0.f, 0.f, 0.f);
            #pragma unroll 1
            for (int i = tid; i < 4224; i += 256) ((float4*)smem)[i] = z4;
            __syncthreads();

            const int grp = w >> 1;          // shift group of this warp's columns
            #pragma unroll
            for (int nj = 0; nj < 4; ++nj) {
                #pragma unroll
                for (int j = 0; j < 2; ++j) {
                    const int c = n0 + 8 * nj + 2 * tig + j;
                    const float bdv = __ldg(bd + c);
                    const int kst = c >> 3;
                    const int pr  = (c >> 2) & 1;
                    const int sl  = c & 3;
                    #pragma unroll
                    for (int mi = 0; mi < 4; ++mi) {
                        #pragma unroll
                        for (int h = 0; h < 2; ++h) {
                            const int r = 16 * mi + g + 8 * h;
                            int D; bool valid;
                            if      (grp == 0) { D = r - 1; valid = (r & 7) >= 1; }
                            else if (grp == 1) { D = r + 1; valid = (r & 7) <= 6; }
                            else if (grp == 2) { D = r - 8; valid = r >= 8; }
                            else               { D = r + 8; valid = r < 56; }
                            if (valid) {
                                const float t = acc[mi][nj][2 * h + j] + bdv;
                                const int mtD = D >> 4, rb = (D >> 3) & 1;
                                const int s = (D & 7) * 4 + sl;
                                const uint32_t addr = sb
                                    + (uint32_t)(mtD * 32 + kst) * ABLK
                                    + (uint32_t)s * 16 + (uint32_t)(pr * 2 + rb) * 4;
                                st32(addr, cvt_tf32(t));
                            }
                        }
                    }
                }
            }
            __syncthreads();   // scatter visible before GEMM2 reads
            #pragma unroll
            for (int mi = 0; mi < 4; ++mi)
                #pragma unroll
                for (int nj = 0; nj < 4; ++nj)
                    #pragma unroll
                    for (int q = 0; q < 4; ++q) acc[mi][nj][q] = 0.0f;
        }
    }

    // ---- epilogue 2: out = xe + up + bu ----
    #pragma unroll
    for (int nj = 0; nj < 4; ++nj) {
        const int C0 = n0 + 8 * nj + 2 * tig;
        const float2 bu2 = *(const float2*)(bu + C0);
        #pragma unroll
        for (int mi = 0; mi < 4; ++mi) {
            #pragma unroll
            for (int h = 0; h < 2; ++h) {
                const int r = 16 * mi + g + 8 * h;
                const float2 xe = *(const float2*)(xb + (size_t)((r >> 3) * 64 + (r & 7)) * CDIM + C0);
                float2 o;
                o.x = acc[mi][nj][2 * h]     + bu2.x + xe.x;
                o.y = acc[mi][nj][2 * h + 1] + bu2.y + xe.y;
                *(float2*)(out + ((size_t)wg * 64 + r) * CDIM + C0) = o;
            }
        }
    }
}

// ---------------- launcher ----------------
extern "C" void kernel_launch(void* const* d_in, const int* in_sizes, int n_in,
                              void* d_out, int out_size) {
    const float* z  = (const float*)d_in[0];
    const float* x  = (const float*)d_in[1];
    const float* Wd = (const float*)d_in[2];
    const float* bd = (const float*)d_in[3];
    const float* Wu = (const float*)d_in[4];
    const float* bu = (const float*)d_in[5];
    float* out = (float*)d_out;

    k_prepw<<<16, 256>>>(Wd, Wu);
    k_zmax<<<256, 256>>>(z);
    k_sim<<<BATCH * NWIN, 256>>>(x);
    k_topk<<<BATCH, 64>>>();

    cudaFuncSetAttribute(k_main, cudaFuncAttributeMaxDynamicSharedMemorySize, SM_TOT);
    k_main<<<BATCH * TOPKN, 256, SM_TOT>>>(x, bd, bu, out);
}

// round 13
// speedup vs baseline: 3.0642x; 1.0430x over previous
#include <cuda_runtime.h>
#include <cuda_bf16.h>
#include <cstdint>
#include <cstddef>

// Problem constants
#define BATCH 32
#define NT    256
#define NS    4096
#define CDIM  256
#define TOPKN 32
#define NWIN  64      // 8x8 windows of 8x8 tokens

// ---------------- device scratch ----------------
__device__ unsigned g_zmaxu[BATCH * CDIM];
__device__ float    g_simw[BATCH * NWIN];
__device__ int      g_idx[BATCH * TOPKN];
__device__ int      g_simcnt[BATCH];
// tf32 fragment-ordered B, linear in global kstep kv (0..63; kv>=32 -> Wu):
// word offset = kv*2048 + ntile*64 + lane*2 + reg   (512KB total, L2-resident)
__device__ __align__(16) uint32_t g_Bt[64 * 2048];

// ---------------- asm helpers ----------------
__device__ __forceinline__ uint32_t s2u(const void* p) {
    uint32_t a;
    asm("{ .reg .u64 t; cvta.to.shared.u64 t, %1; cvt.u32.u64 %0, t; }"
        : "=r"(a) : "l"(p));
    return a;
}

__device__ __forceinline__ uint32_t cvt_tf32(float v) {
    uint32_t u;
    asm("cvt.rna.tf32.f32 %0, %1;" : "=r"(u) : "f"(v));
    return u;
}

__device__ __forceinline__ void st32(uint32_t addr, uint32_t v) {
    asm volatile("st.shared.b32 [%0], %1;" :: "r"(addr), "r"(v) : "memory");
}

__device__ __forceinline__ void lds128(uint32_t* r, uint32_t addr) {
    asm volatile("ld.shared.v4.b32 {%0,%1,%2,%3}, [%4];"
        : "=r"(r[0]), "=r"(r[1]), "=r"(r[2]), "=r"(r[3]) : "r"(addr));
}

__device__ __forceinline__ void mma_tf32(float* c, const uint32_t* a, const uint32_t* b) {
    asm volatile(
        "mma.sync.aligned.m16n8k8.row.col.f32.tf32.tf32.f32 "
        "{%0,%1,%2,%3}, {%4,%5,%6,%7}, {%8,%9}, {%0,%1,%2,%3};"
        : "+f"(c[0]), "+f"(c[1]), "+f"(c[2]), "+f"(c[3])
        : "r"(a[0]), "r"(a[1]), "r"(a[2]), "r"(a[3]), "r"(b[0]), "r"(b[1]));
}

// ordered-uint encoding for float atomicMax
__device__ __forceinline__ unsigned encf(float f) {
    unsigned u = __float_as_uint(f);
    return (u >> 31) ? ~u : (u | 0x80000000u);
}
__device__ __forceinline__ float decf(unsigned u) {
    return __uint_as_float((u >> 31) ? (u & 0x7fffffffu) : ~u);
}

// ---------------- K0: tf32 fragment-permute weights + init zmax/counters ----------------
// grid 16 (= gm*8 + c), block 256: thread = output row n
__global__ void k_prepw(const float* __restrict__ Wd, const float* __restrict__ Wu) {
    const int blk = blockIdx.x;
    const int gm = blk >> 3, c = blk & 7;
    const float* W = gm ? Wu : Wd;
    const int n = threadIdx.x;
    const int nt = n >> 3, gg = n & 7;
    const int cbase = c * 32;
    #pragma unroll
    for (int kl = 0; kl < 32; ++kl) {
        const int ks = kl >> 3;
        const int kk = kl & 7;
        const int lane = gg * 4 + (kk & 3);
        const int reg = kk >> 2;
        const int kv = gm * 32 + c * 4 + ks;
        g_Bt[(size_t)kv * 2048 + nt * 64 + lane * 2 + reg] =
            cvt_tf32(W[n * 256 + cbase + kl]);
    }
    // init zmax atomics (encoding 0 == -inf) and sim completion counters
    const int gid = blk * 256 + n;
    g_zmaxu[gid] = 0u;
    g_zmaxu[gid + 4096] = 0u;
    if (blk == 0 && n < BATCH) g_simcnt[n] = 0;
}

// ---------------- K1: z_max over Nt (parallel, atomic) ----------------
__global__ void k_zmax(const float* __restrict__ z) {
    const int b = blockIdx.x >> 3, rg = blockIdx.x & 7;
    const int c = threadIdx.x;
    const float* zb = z + ((size_t)b * NT + (size_t)rg * 32) * CDIM + c;
    float m = zb[0];
    #pragma unroll 8
    for (int n = 1; n < 32; ++n) m = fmaxf(m, zb[(size_t)n * CDIM]);
    atomicMax(&g_zmaxu[b * CDIM + c], encf(m));
}

// ---------------- K2: per-window mean similarity + fused top-k ----------------
__global__ void k_sim(const float* __restrict__ x) {
    const int bw = blockIdx.x;
    const int b = bw >> 6;
    const int win = bw & 63;
    const int wh = win >> 3, ww = win & 7;

    __shared__ float zm[CDIM];
    __shared__ float tok[64];
    __shared__ int last;

    const int tid = threadIdx.x;
    zm[tid] = decf(g_zmaxu[b * CDIM + tid]);
    __syncthreads();

    const int w = tid >> 5, l = tid & 31;
    const float* xb = x + ((size_t)b * NS + (size_t)wh * 512 + (size_t)ww * 8) * CDIM;
    const float4* zm4 = (const float4*)zm;
    const float4 z0 = zm4[2 * l];
    const float4 z1 = zm4[2 * l + 1];

    #pragma unroll
    for (int m = 0; m < 8; ++m) {
        const float4* row = (const float4*)(xb + (size_t)(w * 64 + m) * CDIM);
        const float4 v0 = row[2 * l];
        const float4 v1 = row[2 * l + 1];
        float a = v0.x * z0.x + v0.y * z0.y + v0.z * z0.z + v0.w * z0.w
                + v1.x * z1.x + v1.y * z1.y + v1.z * z1.z + v1.w * z1.w;
        #pragma unroll
        for (int off = 16; off; off >>= 1) a += __shfl_xor_sync(0xffffffffu, a, off);
        if (l == 0) tok[w * 8 + m] = a;
    }
    __syncthreads();
    if (tid < 32) {
        float v = tok[tid] + tok[tid + 32];
        #pragma unroll
        for (int off = 16; off; off >>= 1) v += __shfl_xor_sync(0xffffffffu, v, off);
        if (tid == 0) {
            g_simw[b * NWIN + win] = v * (1.0f / (256.0f * 64.0f));
            __threadfence();                       // release our sim value
            last = (atomicAdd(&g_simcnt[b], 1) == NWIN - 1);
        }
    }
    __syncthreads();
    if (last) {
        __threadfence();                           // acquire all sims of batch b
        if (tid < NWIN) {
            const float mv = g_simw[b * NWIN + tid];
            int rank = 0;
            #pragma unroll
            for (int j = 0; j < NWIN; ++j) {
                const float vj = g_simw[b * NWIN + j];
                rank += (vj > mv) || (vj == mv && j < tid);
            }
            if (rank < TOPKN) g_idx[b * TOPKN + rank] = tid;
        }
    }
}

// ---------------- K4: fused tf32 mma.sync main (B from L2, prefetch depth 2) ----------------
// SMEM (dynamic): A_perm only: [mt 0..3][kst 0..31] blocks of 528 B = 67584
#define SM_TOT 67584
#define ABLK   528

__global__ void __launch_bounds__(256, 2) k_main(const float* __restrict__ x,
                                                 const float* __restrict__ bd,
                                                 const float* __restrict__ bu,
                                                 float* __restrict__ out) {
    extern __shared__ uint8_t smem[];
    const uint32_t sb = s2u(smem);
    const int tid  = threadIdx.x;
    const int lane = tid & 31;
    const int w    = tid >> 5;            // warp 0..7
    const int n0   = w * 32;              // warp N base
    const int g    = lane >> 2, tig = lane & 3;

    // window base
    const int wg = blockIdx.x;
    const int win = g_idx[(wg >> 5) * TOPKN + (wg & 31)];
    const float* xb = x + ((size_t)(wg >> 5) * NS + (size_t)(win >> 3) * 512 + (size_t)(win & 7) * 8) * CDIM;

    // ---- gather xe (64 rows x 256 ch) into fragment-ordered tf32 A_perm ----
    #pragma unroll 1
    for (int i = 0; i < 16; ++i) {
        const int idx = tid + 256 * i;
        const int row = idx >> 6, c0 = (idx & 63) * 4;
        const float4 v = *(const float4*)(xb + (size_t)((row >> 3) * 64 + (row & 7)) * CDIM + c0);
        const int mt = row >> 4, kst = c0 >> 3;
        const int reg = ((c0 >> 2) & 1) * 2 + ((row >> 3) & 1);
        const uint32_t base = sb + (uint32_t)(mt * 32 + kst) * ABLK
                            + (uint32_t)((row & 7) * 4) * 16 + (uint32_t)reg * 4;
        st32(base +  0, cvt_tf32(v.x));
        st32(base + 16, cvt_tf32(v.y));
        st32(base + 32, cvt_tf32(v.z));
        st32(base + 48, cvt_tf32(v.w));
    }
    __syncthreads();

    const uint32_t aBase = sb + (uint32_t)lane * 16;
    const uint32_t* bp = g_Bt + (size_t)(w * 4) * 64 + (size_t)lane * 2;

    float acc[4][4][4];
    #pragma unroll
    for (int mi = 0; mi < 4; ++mi)
        #pragma unroll
        for (int nj = 0; nj < 4; ++nj)
            #pragma unroll
            for (int q = 0; q < 4; ++q) acc[mi][nj][q] = 0.0f;

    // B fragment ring (depth 4, prefetch distance 2); preload kv=0,1
    uint2 bn[4][4];
    #pragma unroll
    for (int d = 0; d < 2; ++d)
        #pragma unroll
        for (int nj = 0; nj < 4; ++nj)
            bn[d][nj] = __ldg((const uint2*)(bp + (size_t)d * 2048 + (size_t)nj * 64));

    // ---- 64 ksteps: kv 0..31 = GEMM1 (Wd), 32..63 = GEMM2 (Wu) ----
    #pragma unroll 4
    for (int kv = 0; kv < 64; ++kv) {
        // prefetch kv+2
        const int kvp = (kv < 62) ? (kv + 2) : 63;
        #pragma unroll
        for (int nj = 0; nj < 4; ++nj)
            bn[(kv + 2) & 3][nj] = __ldg((const uint2*)(bp + (size_t)kvp * 2048 + (size_t)nj * 64));

        const int kg = kv & 31;
        uint32_t a[4][4];
        #pragma unroll
        for (int mi = 0; mi < 4; ++mi)
            lds128(a[mi], aBase + (uint32_t)(mi * 32 + kg) * ABLK);
        #pragma unroll
        for (int mi = 0; mi < 4; ++mi)
            #pragma unroll
            for (int nj = 0; nj < 4; ++nj)
                mma_tf32(acc[mi][nj], a[mi], (const uint32_t*)&bn[kv & 3][nj]);

        if (kv == 31) {
            // ---- epilogue 1: t = acc + bd; spatial shift; rebuild A_perm ----
            __syncthreads();   // all warps done reading A for GEMM1
            const float4 z4 = make_float4(0.f, 0.f, 0.f, 0.f);
            #pragma unroll 1
            for (int i = tid; i < 4224; i += 256) ((float4*)smem)[i] = z4;
            __syncthreads();

            const int grp = w >> 1;          // shift group of this warp's columns
            #pragma unroll
            for (int nj = 0; nj < 4; ++nj) {
                #pragma unroll
                for (int j = 0; j < 2; ++j) {
                    const int c = n0 + 8 * nj + 2 * tig + j;
                    const float bdv = __ldg(bd + c);
                    const int kst = c >> 3;
                    const int pr  = (c >> 2) & 1;
                    const int sl  = c & 3;
                    #pragma unroll
                    for (int mi = 0; mi < 4; ++mi) {
                        #pragma unroll
                        for (int h = 0; h < 2; ++h) {
                            const int r = 16 * mi + g + 8 * h;
                            int D; bool valid;
                            if      (grp == 0) { D = r - 1; valid = (r & 7) >= 1; }
                            else if (grp == 1) { D = r + 1; valid = (r & 7) <= 6; }
                            else if (grp == 2) { D = r - 8; valid = r >= 8; }
                            else               { D = r + 8; valid = r < 56; }
                            if (valid) {
                                const float t = acc[mi][nj][2 * h + j] + bdv;
                                const int mtD = D >> 4, rb = (D >> 3) & 1;
                                const int s = (D & 7) * 4 + sl;
                                const uint32_t addr = sb
                                    + (uint32_t)(mtD * 32 + kst) * ABLK
                                    + (uint32_t)s * 16 + (uint32_t)(pr * 2 + rb) * 4;
                                st32(addr, cvt_tf32(t));
                            }
                        }
                    }
                }
            }
            __syncthreads();   // scatter visible before GEMM2 reads
            #pragma unroll
            for (int mi = 0; mi < 4; ++mi)
                #pragma unroll
                for (int nj = 0; nj < 4; ++nj)
                    #pragma unroll
                    for (int q = 0; q < 4; ++q) acc[mi][nj][q] = 0.0f;
        }
    }

    // ---- epilogue 2: out = xe + up + bu ----
    #pragma unroll
    for (int nj = 0; nj < 4; ++nj) {
        const int C0 = n0 + 8 * nj + 2 * tig;
        const float2 bu2 = *(const float2*)(bu + C0);
        #pragma unroll
        for (int mi = 0; mi < 4; ++mi) {
            #pragma unroll
            for (int h = 0; h < 2; ++h) {
                const int r = 16 * mi + g + 8 * h;
                const float2 xe = *(const float2*)(xb + (size_t)((r >> 3) * 64 + (r & 7)) * CDIM + C0);
                float2 o;
                o.x = acc[mi][nj][2 * h]     + bu2.x + xe.x;
                o.y = acc[mi][nj][2 * h + 1] + bu2.y + xe.y;
                *(float2*)(out + ((size_t)wg * 64 + r) * CDIM + C0) = o;
            }
        }
    }
}

// ---------------- launcher ----------------
extern "C" void kernel_launch(void* const* d_in, const int* in_sizes, int n_in,
                              void* d_out, int out_size) {
    const float* z  = (const float*)d_in[0];
    const float* x  = (const float*)d_in[1];
    const float* Wd = (const float*)d_in[2];
    const float* bd = (const float*)d_in[3];
    const float* Wu = (const float*)d_in[4];
    const float* bu = (const float*)d_in[5];
    float* out = (float*)d_out;

    k_prepw<<<16, 256>>>(Wd, Wu);
    k_zmax<<<256, 256>>>(z);
    k_sim<<<BATCH * NWIN, 256>>>(x);

    cudaFuncSetAttribute(k_main, cudaFuncAttributeMaxDynamicSharedMemorySize, SM_TOT);
    k_main<<<BATCH * TOPKN, 256, SM_TOT>>>(x, bd, bu, out);
}

// round 14
// speedup vs baseline: 3.2365x; 1.0562x over previous
#include <cuda_runtime.h>
#include <cuda_bf16.h>
#include <cstdint>
#include <cstddef>

// Problem constants
#define BATCH 32
#define NT    256
#define NS    4096
#define CDIM  256
#define TOPKN 32
#define NWIN  64      // 8x8 windows of 8x8 tokens

// ---------------- device scratch ----------------
__device__ unsigned g_zmaxu[BATCH * CDIM];
__device__ float    g_simw[BATCH * NWIN];
__device__ int      g_idx[BATCH * TOPKN];
__device__ int      g_simcnt[BATCH];
// tf32 fragment-ordered B, linear in global kstep kv (0..63; kv>=32 -> Wu):
// word offset = kv*2048 + ntile*64 + lane*2 + reg   (512KB total, L2-resident)
__device__ __align__(16) uint32_t g_Bt[64 * 2048];

// ---------------- asm helpers ----------------
__device__ __forceinline__ uint32_t s2u(const void* p) {
    uint32_t a;
    asm("{ .reg .u64 t; cvta.to.shared.u64 t, %1; cvt.u32.u64 %0, t; }"
        : "=r"(a) : "l"(p));
    return a;
}

__device__ __forceinline__ uint32_t cvt_tf32(float v) {
    uint32_t u;
    asm("cvt.rna.tf32.f32 %0, %1;" : "=r"(u) : "f"(v));
    return u;
}

__device__ __forceinline__ void st32(uint32_t addr, uint32_t v) {
    asm volatile("st.shared.b32 [%0], %1;" :: "r"(addr), "r"(v) : "memory");
}

__device__ __forceinline__ void lds128(uint32_t* r, uint32_t addr) {
    asm volatile("ld.shared.v4.b32 {%0,%1,%2,%3}, [%4];"
        : "=r"(r[0]), "=r"(r[1]), "=r"(r[2]), "=r"(r[3]) : "r"(addr));
}

__device__ __forceinline__ void mma_tf32(float* c, const uint32_t* a, const uint32_t* b) {
    asm volatile(
        "mma.sync.aligned.m16n8k8.row.col.f32.tf32.tf32.f32 "
        "{%0,%1,%2,%3}, {%4,%5,%6,%7}, {%8,%9}, {%0,%1,%2,%3};"
        : "+f"(c[0]), "+f"(c[1]), "+f"(c[2]), "+f"(c[3])
        : "r"(a[0]), "r"(a[1]), "r"(a[2]), "r"(a[3]), "r"(b[0]), "r"(b[1]));
}

// ordered-uint encoding for float atomicMax
__device__ __forceinline__ unsigned encf(float f) {
    unsigned u = __float_as_uint(f);
    return (u >> 31) ? ~u : (u | 0x80000000u);
}
__device__ __forceinline__ float decf(unsigned u) {
    return __uint_as_float((u >> 31) ? (u & 0x7fffffffu) : ~u);
}

// ---------------- K0: tf32 fragment-permute weights + init zmax/counters ----------------
__global__ void k_prepw(const float* __restrict__ Wd, const float* __restrict__ Wu) {
    const int blk = blockIdx.x;
    const int gm = blk >> 3, c = blk & 7;
    const float* W = gm ? Wu : Wd;
    const int n = threadIdx.x;
    const int nt = n >> 3, gg = n & 7;
    const int cbase = c * 32;
    #pragma unroll
    for (int kl = 0; kl < 32; ++kl) {
        const int ks = kl >> 3;
        const int kk = kl & 7;
        const int lane = gg * 4 + (kk & 3);
        const int reg = kk >> 2;
        const int kv = gm * 32 + c * 4 + ks;
        g_Bt[(size_t)kv * 2048 + nt * 64 + lane * 2 + reg] =
            cvt_tf32(W[n * 256 + cbase + kl]);
    }
    const int gid = blk * 256 + n;
    g_zmaxu[gid] = 0u;
    g_zmaxu[gid + 4096] = 0u;
    if (blk == 0 && n < BATCH) g_simcnt[n] = 0;
}

// ---------------- K1: z_max over Nt (parallel, atomic) ----------------
__global__ void k_zmax(const float* __restrict__ z) {
    const int b = blockIdx.x >> 3, rg = blockIdx.x & 7;
    const int c = threadIdx.x;
    const float* zb = z + ((size_t)b * NT + (size_t)rg * 32) * CDIM + c;
    float m = zb[0];
    #pragma unroll 8
    for (int n = 1; n < 32; ++n) m = fmaxf(m, zb[(size_t)n * CDIM]);
    atomicMax(&g_zmaxu[b * CDIM + c], encf(m));
}

// ---------------- K2: per-window mean similarity + fused top-k ----------------
__global__ void k_sim(const float* __restrict__ x) {
    const int bw = blockIdx.x;
    const int b = bw >> 6;
    const int win = bw & 63;
    const int wh = win >> 3, ww = win & 7;

    __shared__ float zm[CDIM];
    __shared__ float tok[64];
    __shared__ int last;

    const int tid = threadIdx.x;
    zm[tid] = decf(g_zmaxu[b * CDIM + tid]);
    __syncthreads();

    const int w = tid >> 5, l = tid & 31;
    const float* xb = x + ((size_t)b * NS + (size_t)wh * 512 + (size_t)ww * 8) * CDIM;
    const float4* zm4 = (const float4*)zm;
    const float4 z0 = zm4[2 * l];
    const float4 z1 = zm4[2 * l + 1];

    #pragma unroll
    for (int m = 0; m < 8; ++m) {
        const float4* row = (const float4*)(xb + (size_t)(w * 64 + m) * CDIM);
        const float4 v0 = row[2 * l];
        const float4 v1 = row[2 * l + 1];
        float a = v0.x * z0.x + v0.y * z0.y + v0.z * z0.z + v0.w * z0.w
                + v1.x * z1.x + v1.y * z1.y + v1.z * z1.z + v1.w * z1.w;
        #pragma unroll
        for (int off = 16; off; off >>= 1) a += __shfl_xor_sync(0xffffffffu, a, off);
        if (l == 0) tok[w * 8 + m] = a;
    }
    __syncthreads();
    if (tid < 32) {
        float v = tok[tid] + tok[tid + 32];
        #pragma unroll
        for (int off = 16; off; off >>= 1) v += __shfl_xor_sync(0xffffffffu, v, off);
        if (tid == 0) {
            g_simw[b * NWIN + win] = v * (1.0f / (256.0f * 64.0f));
            __threadfence();
            last = (atomicAdd(&g_simcnt[b], 1) == NWIN - 1);
        }
    }
    __syncthreads();
    if (last) {
        __threadfence();
        if (tid < NWIN) {
            const float mv = g_simw[b * NWIN + tid];
            int rank = 0;
            #pragma unroll
            for (int j = 0; j < NWIN; ++j) {
                const float vj = g_simw[b * NWIN + j];
                rank += (vj > mv) || (vj == mv && j < tid);
            }
            if (rank < TOPKN) g_idx[b * TOPKN + rank] = tid;
        }
    }
}

// ---------------- K4: fused tf32 mma.sync main ----------------
// SMEM (dynamic): A_perm only: [mt 0..3][kst 0..31] blocks of 528 B = 67584
#define SM_TOT 67584
#define ABLK   528

__global__ void __launch_bounds__(256, 2) k_main(const float* __restrict__ x,
                                                 const float* __restrict__ bd,
                                                 const float* __restrict__ bu,
                                                 float* __restrict__ out) {
    extern __shared__ uint8_t smem[];
    const uint32_t sb = s2u(smem);
    const int tid  = threadIdx.x;
    const int lane = tid & 31;
    const int w    = tid >> 5;            // warp 0..7
    const int n0   = w * 32;              // warp N base
    const int g    = lane >> 2, tig = lane & 3;

    // window base
    const int wg = blockIdx.x;
    const int win = g_idx[(wg >> 5) * TOPKN + (wg & 31)];
    const float* xb = x + ((size_t)(wg >> 5) * NS + (size_t)(win >> 3) * 512 + (size_t)(win & 7) * 8) * CDIM;

    // ---- gather xe (64 rows x 256 ch) into fragment-ordered tf32 A_perm ----
    #pragma unroll 1
    for (int i = 0; i < 16; ++i) {
        const int idx = tid + 256 * i;
        const int row = idx >> 6, c0 = (idx & 63) * 4;
        const float4 v = *(const float4*)(xb + (size_t)((row >> 3) * 64 + (row & 7)) * CDIM + c0);
        const int mt = row >> 4, kst = c0 >> 3;
        const int reg = ((c0 >> 2) & 1) * 2 + ((row >> 3) & 1);
        const uint32_t base = sb + (uint32_t)(mt * 32 + kst) * ABLK
                            + (uint32_t)((row & 7) * 4) * 16 + (uint32_t)reg * 4;
        st32(base +  0, cvt_tf32(v.x));
        st32(base + 16, cvt_tf32(v.y));
        st32(base + 32, cvt_tf32(v.z));
        st32(base + 48, cvt_tf32(v.w));
    }
    __syncthreads();

    const uint32_t aBase = sb + (uint32_t)lane * 16;
    const uint32_t* bp = g_Bt + (size_t)(w * 4) * 64 + (size_t)lane * 2;

    float acc[4][4][4];
    #pragma unroll
    for (int mi = 0; mi < 4; ++mi)
        #pragma unroll
        for (int nj = 0; nj < 4; ++nj)
            #pragma unroll
            for (int q = 0; q < 4; ++q) acc[mi][nj][q] = 0.0f;

    // B fragment ring (depth 2, prefetch distance 1); preload kv=0
    uint2 bn[2][4];
    #pragma unroll
    for (int nj = 0; nj < 4; ++nj)
        bn[0][nj] = __ldg((const uint2*)(bp + (size_t)nj * 64));

    // ---- GEMM1: kv 0..31 (Wd), branch-free ----
    #pragma unroll 4
    for (int kg = 0; kg < 32; ++kg) {
        // prefetch kv+1 (kg=31 prefetches kv=32 — GEMM2's first, covered by epilogue)
        #pragma unroll
        for (int nj = 0; nj < 4; ++nj)
            bn[(kg + 1) & 1][nj] = __ldg((const uint2*)(bp + (size_t)(kg + 1) * 2048 + (size_t)nj * 64));
        uint32_t a[4][4];
        #pragma unroll
        for (int mi = 0; mi < 4; ++mi)
            lds128(a[mi], aBase + (uint32_t)(mi * 32 + kg) * ABLK);
        #pragma unroll
        for (int mi = 0; mi < 4; ++mi)
            #pragma unroll
            for (int nj = 0; nj < 4; ++nj)
                mma_tf32(acc[mi][nj], a[mi], (const uint32_t*)&bn[kg & 1][nj]);
    }

    // ---- epilogue 1: t = acc + bd; spatial shift; rebuild A_perm ----
    __syncthreads();   // all warps done reading A for GEMM1
    {
        const float4 z4 = make_float4(0.f, 0.f, 0.f, 0.f);
        #pragma unroll 1
        for (int i = tid; i < 4224; i += 256) ((float4*)smem)[i] = z4;
    }
    __syncthreads();
    {
        const int grp = w >> 1;          // shift group of this warp's columns
        #pragma unroll
        for (int nj = 0; nj < 4; ++nj) {
            #pragma unroll
            for (int j = 0; j < 2; ++j) {
                const int c = n0 + 8 * nj + 2 * tig + j;
                const float bdv = __ldg(bd + c);
                const int kst = c >> 3;
                const int pr  = (c >> 2) & 1;
                const int sl  = c & 3;
                #pragma unroll
                for (int mi = 0; mi < 4; ++mi) {
                    #pragma unroll
                    for (int h = 0; h < 2; ++h) {
                        const int r = 16 * mi + g + 8 * h;
                        int D; bool valid;
                        if      (grp == 0) { D = r - 1; valid = (r & 7) >= 1; }
                        else if (grp == 1) { D = r + 1; valid = (r & 7) <= 6; }
                        else if (grp == 2) { D = r - 8; valid = r >= 8; }
                        else               { D = r + 8; valid = r < 56; }
                        if (valid) {
                            const float t = acc[mi][nj][2 * h + j] + bdv;
                            const int mtD = D >> 4, rb = (D >> 3) & 1;
                            const int s = (D & 7) * 4 + sl;
                            const uint32_t addr = sb
                                + (uint32_t)(mtD * 32 + kst) * ABLK
                                + (uint32_t)s * 16 + (uint32_t)(pr * 2 + rb) * 4;
                            st32(addr, cvt_tf32(t));
                        }
                    }
                }
            }
        }
    }
    __syncthreads();   // scatter visible before GEMM2 reads
    #pragma unroll
    for (int mi = 0; mi < 4; ++mi)
        #pragma unroll
        for (int nj = 0; nj < 4; ++nj)
            #pragma unroll
            for (int q = 0; q < 4; ++q) acc[mi][nj][q] = 0.0f;

    // ---- GEMM2: kv 32..63 (Wu), branch-free ----
    // slot parity: kv=32+kg -> slot (kg & 1); kv=32 already prefetched above.
    const uint32_t* bp2 = bp + (size_t)32 * 2048;
    #pragma unroll 4
    for (int kg = 0; kg < 32; ++kg) {
        const int kgp = (kg < 31) ? (kg + 1) : 31;
        #pragma unroll
        for (int nj = 0; nj < 4; ++nj)
            bn[(kg + 1) & 1][nj] = __ldg((const uint2*)(bp2 + (size_t)kgp * 2048 + (size_t)nj * 64));
        uint32_t a[4][4];
        #pragma unroll
        for (int mi = 0; mi < 4; ++mi)
            lds128(a[mi], aBase + (uint32_t)(mi * 32 + kg) * ABLK);
        #pragma unroll
        for (int mi = 0; mi < 4; ++mi)
            #pragma unroll
            for (int nj = 0; nj < 4; ++nj)
                mma_tf32(acc[mi][nj], a[mi], (const uint32_t*)&bn[kg & 1][nj]);
    }

    // ---- epilogue 2: out = xe + up + bu ----
    #pragma unroll
    for (int nj = 0; nj < 4; ++nj) {
        const int C0 = n0 + 8 * nj + 2 * tig;
        const float2 bu2 = *(const float2*)(bu + C0);
        #pragma unroll
        for (int mi = 0; mi < 4; ++mi) {
            #pragma unroll
            for (int h = 0; h < 2; ++h) {
                const int r = 16 * mi + g + 8 * h;
                const float2 xe = *(const float2*)(xb + (size_t)((r >> 3) * 64 + (r & 7)) * CDIM + C0);
                float2 o;
                o.x = acc[mi][nj][2 * h]     + bu2.x + xe.x;
                o.y = acc[mi][nj][2 * h + 1] + bu2.y + xe.y;
                *(float2*)(out + ((size_t)wg * 64 + r) * CDIM + C0) = o;
            }
        }
    }
}

// ---------------- launcher ----------------
extern "C" void kernel_launch(void* const* d_in, const int* in_sizes, int n_in,
                              void* d_out, int out_size) {
    const float* z  = (const float*)d_in[0];
    const float* x  = (const float*)d_in[1];
    const float* Wd = (const float*)d_in[2];
    const float* bd = (const float*)d_in[3];
    const float* Wu = (const float*)d_in[4];
    const float* bu = (const float*)d_in[5];
    float* out = (float*)d_out;

    k_prepw<<<16, 256>>>(Wd, Wu);
    k_zmax<<<256, 256>>>(z);
    k_sim<<<BATCH * NWIN, 256>>>(x);

    cudaFuncSetAttribute(k_main, cudaFuncAttributeMaxDynamicSharedMemorySize, SM_TOT);
    k_main<<<BATCH * TOPKN, 256, SM_TOT>>>(x, bd, bu, out);
}